// round 15
// baseline (speedup 1.0000x reference)
#include <cuda_runtime.h>
#include <cuda_bf16.h>
#include <math.h>
#include <stdint.h>

#define BB   64
#define LL   512
#define CC   256
#define HH   8
#define DHH  32
#define NTOK (BB*LL)

// ---------------- scratch (static __device__, no allocations) ----------------
__device__ float g_s1[(size_t)NTOK*CC];       // scorer hidden (fp32)
__device__ float g_z[BB*LL];                  // raw scores
__device__ float g_sv[BB*LL];                 // y_soft values (jax-replicated)
__device__ unsigned char g_tier2[BB*LL];      // token_mask residue flag
__device__ int   g_kper[BB];
__device__ int   g_kmax;
__device__ int   g_topk[BB*LL];
__device__ float g_h[(size_t)NTOK*CC];        // fp32 residual-scaled hidden
// bf16 operands for tensor-core GEMMs / attention
__device__ __nv_bfloat16 g_qkvb[(size_t)NTOK*3*CC];
__device__ __nv_bfloat16 g_hcb [(size_t)NTOK*CC];
__device__ __nv_bfloat16 g_aob [(size_t)NTOK*CC];
__device__ __nv_bfloat16 g_hb  [(size_t)NTOK*CC];
__device__ __nv_bfloat16 g_midb[(size_t)NTOK*2*CC];
__device__ __nv_bfloat16 g_Winb [3*CC*CC];
__device__ __nv_bfloat16 g_Woutb[CC*CC];
__device__ __nv_bfloat16 g_Wm1b [2*CC*CC];
__device__ __nv_bfloat16 g_Wm2b [CC*2*CC];

// ---------------- helpers -----------------------------------------------------
__device__ __forceinline__ uint32_t smem_u32(const void* p){
    uint32_t a;
    asm("{ .reg .u64 t; cvta.to.shared.u64 t, %1; cvt.u32.u64 %0, t; }" : "=r"(a) : "l"(p));
    return a;
}
__device__ __forceinline__ uint32_t pk(float a, float b){
    __nv_bfloat162 t = __floats2bfloat162_rn(a, b);
    return *reinterpret_cast<uint32_t*>(&t);
}
__device__ __forceinline__ void ldsm4(uint32_t& r0, uint32_t& r1, uint32_t& r2, uint32_t& r3,
                                      uint32_t addr){
    asm volatile("ldmatrix.sync.aligned.m8n8.x4.shared.b16 {%0,%1,%2,%3}, [%4];"
                 : "=r"(r0), "=r"(r1), "=r"(r2), "=r"(r3) : "r"(addr));
}
__device__ __forceinline__ void mma_bf16(float* c, const uint32_t* a, const uint32_t* b){
    asm volatile("mma.sync.aligned.m16n8k16.row.col.f32.bf16.bf16.f32 "
                 "{%0,%1,%2,%3}, {%4,%5,%6,%7}, {%8,%9}, {%0,%1,%2,%3};"
                 : "+f"(c[0]), "+f"(c[1]), "+f"(c[2]), "+f"(c[3])
                 : "r"(a[0]), "r"(a[1]), "r"(a[2]), "r"(a[3]), "r"(b[0]), "r"(b[1]));
}
__device__ __forceinline__ void cp16(uint32_t dst, const void* src){
    asm volatile("cp.async.cg.shared.global [%0], [%1], 16;" :: "r"(dst), "l"(src) : "memory");
}
#define CP_COMMIT() asm volatile("cp.async.commit_group;" ::: "memory")
#define CP_WAIT0()  asm volatile("cp.async.wait_group 0;"  ::: "memory")
// packed fp32x2 FMA — two independent IEEE fp32 rn FMAs, bit-identical to fmaf
__device__ __forceinline__ void ffma2(uint64_t& c, uint64_t a, uint64_t b){
    asm volatile("fma.rn.f32x2 %0, %1, %2, %0;" : "+l"(c) : "l"(a), "l"(b));
}
__device__ __forceinline__ uint64_t pk64(float lo, float hi){
    uint64_t v;
    asm("mov.b64 %0, {%1, %2};" : "=l"(v) : "f"(lo), "f"(hi));
    return v;
}
__device__ __forceinline__ void unpk64(float& lo, float& hi, uint64_t v){
    asm("mov.b64 {%0, %1}, %2;" : "=f"(lo), "=f"(hi) : "l"(v));
}

// ---------------- warp-MMA bf16 GEMM: out = act(A@W^T + bias) (+res/+scatter) -
// BK=64, 2-stage cp.async, dynamic smem. K multiple of 64.
#define SROW 72                      // smem row stride in bf16 (144B, bank-clean)
#define STAGEB (128*SROW*2)          // one stage, one array: 18432 B
#define GSMEM  (4*STAGEB)            // A(2 stages) + B(2 stages) = 73728 B

template<int ACT, int RES, int OUTBF, int SCAT>
__global__ __launch_bounds__(256)
void wmma_gemm(const __nv_bfloat16* __restrict__ A, const __nv_bfloat16* __restrict__ W,
               const float* __restrict__ bias, const float* __restrict__ res,
               float* __restrict__ outf, __nv_bfloat16* __restrict__ outb,
               const float* __restrict__ ratio,
               int M, int N, int K)
{
    extern __shared__ __align__(16) char smem_dyn[];
    const uint32_t as_b = smem_u32(smem_dyn);              // A: stages 0,1
    const uint32_t bs_b = as_b + 2*STAGEB;                 // B: stages 0,1
    const int tid  = threadIdx.x;
    const int wid  = tid >> 5, lane = tid & 31;
    const int bm   = blockIdx.y << 7;
    const int bn   = blockIdx.x << 7;
    const int wm   = wid & 3;
    const int wn   = wid >> 2;

    // global->smem mapping: 4 iterations per array, 16B per thread per iter
    // idx = tid + it*256 ; row = idx>>3 (0..127), c16 = idx&7 (16B column)
    const uint32_t a_row = (uint32_t)(wm*32 + (lane & 15));
    const uint32_t a_kad = (uint32_t)((lane >> 4) << 3);
    const uint32_t b_row = (uint32_t)(wn*64 + ((lane >> 4) << 3) + (lane & 7));
    const uint32_t b_kad = (uint32_t)(((lane >> 3) & 1) << 3);

    float acc[2][8][4];
#pragma unroll
    for (int i = 0; i < 2; i++)
#pragma unroll
        for (int j = 0; j < 8; j++)
#pragma unroll
            for (int q = 0; q < 4; q++) acc[i][j][q] = 0.f;

    const int nc = K >> 6;
    // prologue: stage 0 (k0 = 0)
#pragma unroll
    for (int it = 0; it < 4; it++) {
        int idx = tid + it*256;
        int row = idx >> 3, c16 = idx & 7;
        uint32_t so = (uint32_t)(row*SROW + c16*8) * 2;
        cp16(as_b + so, A + (size_t)(bm + row) * K + c16*8);
        cp16(bs_b + so, W + (size_t)(bn + row) * K + c16*8);
    }
    CP_COMMIT();

    for (int c = 0; c < nc; c++) {
        CP_WAIT0();
        __syncthreads();
        if (c + 1 < nc) {
            const int k1 = (c + 1) << 6;
            const uint32_t sb = ((c + 1) & 1) * STAGEB;
#pragma unroll
            for (int it = 0; it < 4; it++) {
                int idx = tid + it*256;
                int row = idx >> 3, c16 = idx & 7;
                uint32_t so = sb + (uint32_t)(row*SROW + c16*8) * 2;
                cp16(as_b + so, A + (size_t)(bm + row) * K + k1 + c16*8);
                cp16(bs_b + so, W + (size_t)(bn + row) * K + k1 + c16*8);
            }
            CP_COMMIT();
        }
        const uint32_t ab = as_b + (c & 1) * STAGEB;
        const uint32_t bb = bs_b + (c & 1) * STAGEB;
#pragma unroll
        for (int ks = 0; ks < 4; ks++) {
            const uint32_t kcol = (uint32_t)(ks << 4);
            uint32_t a[2][4];
#pragma unroll
            for (int tm = 0; tm < 2; tm++) {
                uint32_t ad = ab + ((a_row + tm*16) * SROW + kcol + a_kad) * 2;
                ldsm4(a[tm][0], a[tm][1], a[tm][2], a[tm][3], ad);
            }
            uint32_t b[8][2];
#pragma unroll
            for (int tp = 0; tp < 4; tp++) {
                uint32_t bd = bb + ((b_row + tp*16) * SROW + kcol + b_kad) * 2;
                ldsm4(b[2*tp][0], b[2*tp][1], b[2*tp+1][0], b[2*tp+1][1], bd);
            }
#pragma unroll
            for (int tm = 0; tm < 2; tm++)
#pragma unroll
                for (int tn = 0; tn < 8; tn++)
                    mma_bf16(acc[tm][tn], a[tm], b[tn]);
        }
        __syncthreads();
    }

    if (SCAT) {
        const int kmax = g_kmax;
#pragma unroll
        for (int tm = 0; tm < 2; tm++) {
#pragma unroll
            for (int half = 0; half < 2; half++) {
                const int m = bm + wm*32 + tm*16 + (lane >> 2) + half*8;
                const int b = m >> 9, j = m & 511;
                if (j >= kmax) continue;
                const int dst = g_topk[m];
                const size_t node = (((size_t)b << 9) + dst) * CC;
                const float r = ratio[b];
#pragma unroll
                for (int tn = 0; tn < 8; tn++) {
                    const int gn = bn + wn*64 + tn*8 + ((lane & 3) << 1);
                    float v0 = acc[tm][tn][2*half+0] + bias[gn];
                    float v1 = acc[tm][tn][2*half+1] + bias[gn+1];
                    float2 xv = *(const float2*)(res + node + gn);
                    v0 = (v0 + xv.x) * r;
                    v1 = (v1 + xv.y) * r;
                    *(float2*)(g_h + node + gn) = make_float2(v0, v1);
                    *(uint32_t*)(g_hb + node + gn) = pk(v0, v1);
                }
            }
        }
        return;
    }

#pragma unroll
    for (int tm = 0; tm < 2; tm++) {
        const int gm = bm + wm*32 + tm*16 + (lane >> 2);
#pragma unroll
        for (int tn = 0; tn < 8; tn++) {
            const int gn = bn + wn*64 + tn*8 + ((lane & 3) << 1);
            const float b0 = bias[gn], b1 = bias[gn+1];
#pragma unroll
            for (int half = 0; half < 2; half++) {
                const int m = gm + half*8;
                float v0 = acc[tm][tn][2*half+0] + b0;
                float v1 = acc[tm][tn][2*half+1] + b1;
                if (ACT) { v0 = fmaxf(v0, 0.f); v1 = fmaxf(v1, 0.f); }
                const size_t o = (size_t)m * N + gn;
                if (RES) {
                    float2 r = *(const float2*)(res + o);
                    v0 += r.x; v1 += r.y;
                }
                if (OUTBF) *(uint32_t*)(outb + o) = pk(v0, v1);
                else       *(float2*)(outf + o)   = make_float2(v0, v1);
            }
        }
    }
}

// ---------------- fp32 SIMT GEMM (scorer only — selection-critical) ----------
template<int ACT>
__global__ __launch_bounds__(256)
void gemm_kernel(const float* __restrict__ A, const float* __restrict__ W,
                 const float* __restrict__ bias,
                 float* __restrict__ out, int M, int N, int K)
{
    __shared__ float As[8][132];
    __shared__ float Bs[8][132];
    const int tid = threadIdx.x;
    const int tx = tid & 15, ty = tid >> 4;
    const int bm = blockIdx.y << 7, bn = blockIdx.x << 7;
    const int lr = tid >> 1;
    const int lc = (tid & 1) << 2;

    uint64_t acc2[8][4];
#pragma unroll
    for (int i = 0; i < 8; i++)
#pragma unroll
        for (int j = 0; j < 4; j++) acc2[i][j] = 0ull;

    const float* Ap = A + (size_t)(bm + lr) * K + lc;
    const float* Wp = W + (size_t)(bn + lr) * K + lc;

    float4 av = *(const float4*)Ap;
    float4 wv = *(const float4*)Wp;

    for (int k0 = 0; k0 < K; k0 += 8) {
        __syncthreads();
        As[lc+0][lr]=av.x; As[lc+1][lr]=av.y; As[lc+2][lr]=av.z; As[lc+3][lr]=av.w;
        Bs[lc+0][lr]=wv.x; Bs[lc+1][lr]=wv.y; Bs[lc+2][lr]=wv.z; Bs[lc+3][lr]=wv.w;
        __syncthreads();
        if (k0 + 8 < K) {
            av = *(const float4*)(Ap + k0 + 8);
            wv = *(const float4*)(Wp + k0 + 8);
        }
#pragma unroll
        for (int kk = 0; kk < 8; kk++) {
            float a[8], b[8];
            *(float4*)&a[0] = *(const float4*)&As[kk][ty*8];
            *(float4*)&a[4] = *(const float4*)&As[kk][ty*8+4];
            *(float4*)&b[0] = *(const float4*)&Bs[kk][tx*8];
            *(float4*)&b[4] = *(const float4*)&Bs[kk][tx*8+4];
            uint64_t bp[4];
#pragma unroll
            for (int j = 0; j < 4; j++) bp[j] = pk64(b[2*j], b[2*j+1]);
#pragma unroll
            for (int i = 0; i < 8; i++) {
                const uint64_t ad = pk64(a[i], a[i]);
#pragma unroll
                for (int j = 0; j < 4; j++)
                    ffma2(acc2[i][j], ad, bp[j]);
            }
        }
    }

#pragma unroll
    for (int i = 0; i < 8; i++) {
        const size_t m = (size_t)bm + ty*8 + i;
#pragma unroll
        for (int j4 = 0; j4 < 2; j4++) {
            const int n = bn + tx*8 + j4*4;
            float c0, c1, c2, c3;
            unpk64(c0, c1, acc2[i][2*j4+0]);
            unpk64(c2, c3, acc2[i][2*j4+1]);
            float v[4] = {c0, c1, c2, c3};
#pragma unroll
            for (int j = 0; j < 4; j++) {
                float t = v[j] + bias[n+j];
                if (ACT) t = fmaxf(t, 0.f);
                v[j] = t;
            }
            *(float4*)(out + m*N + n) = make_float4(v[0],v[1],v[2],v[3]);
        }
    }
}

// ---------------- weights fp32 -> bf16, all four in one launch ----------------
__global__ __launch_bounds__(256)
void f2bf4_kernel(const float* __restrict__ Win,  __nv_bfloat16* __restrict__ dWin,
                  const float* __restrict__ Wout, __nv_bfloat16* __restrict__ dWout,
                  const float* __restrict__ Wm1,  __nv_bfloat16* __restrict__ dWm1,
                  const float* __restrict__ Wm2,  __nv_bfloat16* __restrict__ dWm2)
{
    int blk = blockIdx.x;
    const float* s; __nv_bfloat16* d; int off;
    if      (blk < 192) { s = Win;  d = dWin;  off = blk;       }
    else if (blk < 256) { s = Wout; d = dWout; off = blk - 192; }
    else if (blk < 384) { s = Wm1;  d = dWm1;  off = blk - 256; }
    else                { s = Wm2;  d = dWm2;  off = blk - 384; }
    int i = off * 256 + threadIdx.x;
    float4 v = ((const float4*)s)[i];
    uint2 p; p.x = pk(v.x, v.y); p.y = pk(v.z, v.w);
    ((uint2*)d)[i] = p;
}

// ---------------- raw scores: z[n] = s1[n]·Ws2 + bs2 --------------------------
__global__ __launch_bounds__(256)
void score_kernel(const float* __restrict__ Ws2, const float* __restrict__ bs2)
{
    int gid  = blockIdx.x * 256 + threadIdx.x;
    int n    = gid >> 5;
    int lane = gid & 31;
    const float4* r4 = (const float4*)(g_s1 + (size_t)n * CC);
    const float4* w4 = (const float4*)Ws2;
    float4 a0 = r4[lane*2],   b0 = w4[lane*2];
    float4 a1 = r4[lane*2+1], b1 = w4[lane*2+1];
    float s = a0.x*b0.x + a0.y*b0.y + a0.z*b0.z + a0.w*b0.w
            + a1.x*b1.x + a1.y*b1.y + a1.z*b1.z + a1.w*b1.w;
#pragma unroll
    for (int o = 16; o; o >>= 1) s += __shfl_down_sync(0xffffffffu, s, o);
    if (lane == 0) g_z[n] = s + bs2[0];
}

// ---------------- jax-replicated softmax pipeline + tier flag -----------------
__global__ __launch_bounds__(512)
void softmax_kernel(const float* __restrict__ gumbel)
{
    __shared__ float red[512];
    const int b = blockIdx.x, t = threadIdx.x;
    const int n = b * 512 + t;
    float sc = g_z[n];

    red[t] = sc; __syncthreads();
#pragma unroll
    for (int s = 256; s; s >>= 1) { if (t < s) red[t] = fmaxf(red[t], red[t+s]); __syncthreads(); }
    float m1 = red[0]; __syncthreads();

    float sh = __fadd_rn(sc, -m1);
    float e1 = expf(sh);
    red[t] = e1; __syncthreads();
#pragma unroll
    for (int s = 256; s; s >>= 1) { if (t < s) red[t] = __fadd_rn(red[t], red[t+s]); __syncthreads(); }
    float L = logf(red[0]); __syncthreads();

    float ls = __fadd_rn(sh, -L);
    float z  = __fadd_rn(ls, gumbel[n]);
    red[t] = z; __syncthreads();
#pragma unroll
    for (int s = 256; s; s >>= 1) { if (t < s) red[t] = fmaxf(red[t], red[t+s]); __syncthreads(); }
    float m2 = red[0]; __syncthreads();

    float e2 = expf(__fadd_rn(z, -m2));
    red[t] = e2; __syncthreads();
#pragma unroll
    for (int s = 256; s; s >>= 1) { if (t < s) red[t] = __fadd_rn(red[t], red[t+s]); __syncthreads(); }
    float S = red[0];

    float sval = __fdiv_rn(e2, S);
    g_sv[n] = sval;
    float tt = __fadd_rn(__fadd_rn(1.0f, sval), -sval);
    g_tier2[n] = (tt != 1.0f) ? 1 : 0;
}

// ---------------- k_per / k_max ----------------------------------------------
__global__ void kper_kernel(const float* __restrict__ ratio)
{
    __shared__ int sm[64];
    int b = threadIdx.x;
    int kp = (int)ceilf(ratio[b] * 512.0f);
    if (kp < 1)  kp = 1;
    if (kp > LL) kp = LL;
    g_kper[b] = kp;
    sm[b] = kp;
    __syncthreads();
    for (int s = 32; s > 0; s >>= 1) {
        if (b < s) sm[b] = max(sm[b], sm[b+s]);
        __syncthreads();
    }
    if (b == 0) g_kmax = sm[0];
}

// ---------------- per-batch selection (tier-aware, replicates reference) ------
__global__ __launch_bounds__(512)
void topk_kernel()
{
    __shared__ float sv[512];
    __shared__ int   si[512];
    __shared__ int   sfl[512];
    __shared__ int   sA[512];
    const int b = blockIdx.x, t = threadIdx.x;
    sv[t] = g_sv[b*512 + t];
    si[t] = t;
    __syncthreads();
    for (int k = 2; k <= 512; k <<= 1) {
        for (int j = k >> 1; j > 0; j >>= 1) {
            int ixj = t ^ j;
            if (ixj > t) {
                bool desc = ((t & k) == 0);
                float v1 = sv[t], v2 = sv[ixj];
                int   i1 = si[t], i2 = si[ixj];
                bool less = (v1 < v2) || (v1 == v2 && i1 > i2);
                bool sw = desc ? less : !less;
                if (sw) {
                    sv[t] = v2; sv[ixj] = v1;
                    si[t] = i2; si[ixj] = i1;
                }
            }
            __syncthreads();
        }
    }
    const int kmax = g_kmax;
    const int kper = g_kper[b];
    sfl[si[t]] = (t < kmax) ? 1 : 0;
    __syncthreads();
    const int sel   = sfl[t];
    const int tier2 = (int)g_tier2[b*512 + t];
    const int a1 = sel & (tier2 ^ 1);
    const int a2 = sel & tier2;
    sA[t] = a1 | (a2 << 16);
    __syncthreads();
    for (int off = 1; off < 512; off <<= 1) {
        int add = (t >= off) ? sA[t-off] : 0;
        __syncthreads();
        sA[t] += add;
        __syncthreads();
    }
    const int inc1 = sA[t] & 0xffff, inc2 = sA[t] >> 16;
    const int n1   = sA[511] & 0xffff;
    const int excl1 = inc1 - a1, excl2 = inc2 - a2;
    const int kept = (a1 && excl1 < kper) || (a2 && (n1 + excl2) < kper);
    const int nk = 1 - kept;
    __syncthreads();
    sA[t] = kept | (nk << 16);
    __syncthreads();
    for (int off = 1; off < 512; off <<= 1) {
        int add = (t >= off) ? sA[t-off] : 0;
        __syncthreads();
        sA[t] += add;
        __syncthreads();
    }
    const int rk = (sA[t] & 0xffff) - kept;
    const int rn = (sA[t] >> 16) - nk;
    if (kept) g_topk[b*512 + rk] = t;
    else      g_topk[b*512 + kper + rn] = t;
}

// ---------------- gather -> bf16 h_compact (4 rows / 256-thread block) --------
__global__ __launch_bounds__(256)
void gather_kernel(const float* __restrict__ x)
{
    int row = blockIdx.x * 4 + (threadIdx.x >> 6);
    int b = row >> 9, j = row & 511;
    int t = threadIdx.x & 63;
    uint2* dst = (uint2*)(g_hcb + (size_t)row * CC);
    if (j < g_kper[b]) {
        int src = g_topk[row];
        float4 v = ((const float4*)(x + ((size_t)b*512 + src) * CC))[t];
        uint2 o; o.x = pk(v.x, v.y); o.y = pk(v.z, v.w);
        dst[t] = o;
    } else {
        dst[t] = make_uint2(0u, 0u);
    }
}

// ---------------- flash attention v2 on HMMA (bf16 in, fp32 accum) ------------
#define QS 40   // Q/K smem stride (bf16)
#define VS 72   // Vt smem stride (bf16)
__global__ __launch_bounds__(128)
void attn_mma_kernel()
{
    __shared__ __align__(16) __nv_bfloat16 Qs[64*QS];
    __shared__ __align__(16) __nv_bfloat16 Ks[64*QS];
    __shared__ __align__(16) __nv_bfloat16 Vt[32*VS];
    const uint32_t qs_b = smem_u32(Qs);
    const uint32_t ks_b = smem_u32(Ks);
    const uint32_t vt_b = smem_u32(Vt);

    const int bh = blockIdx.x;
    const int b = bh >> 3, h = bh & 7;
    const int q0 = blockIdx.y << 6;
    const int tid = threadIdx.x;
    const int wid = tid >> 5, lane = tid & 31;
    const int kper = g_kper[b];
    const size_t base = (size_t)b * 512;
    const int hq = h * 32;

#pragma unroll
    for (int i = 0; i < 2; i++) {
        int idx = tid + i*128;
        int row = idx >> 2, qt = idx & 3;
        const uint4 v = *(const uint4*)(g_qkvb + (base + q0 + row) * 768 + hq + qt*8);
        *(uint4*)((char*)Qs + (row*QS + qt*8)*2) = v;
    }

    const uint32_t a_row = (uint32_t)(wid*16 + (lane & 15));
    const uint32_t a_kad = (uint32_t)((lane >> 4) << 3);
    const uint32_t b_rw  = (uint32_t)(((lane >> 4) << 3) + (lane & 7));
    const uint32_t b_kad = (uint32_t)(((lane >> 3) & 1) << 3);
    __syncthreads();
    uint32_t aq[2][4];
#pragma unroll
    for (int ks = 0; ks < 2; ks++)
        ldsm4(aq[ks][0], aq[ks][1], aq[ks][2], aq[ks][3],
              qs_b + (a_row*QS + ks*16 + a_kad)*2);

    float co[4][4];
#pragma unroll
    for (int i = 0; i < 4; i++)
#pragma unroll
        for (int j = 0; j < 4; j++) co[i][j] = 0.f;
    float m0 = -1e30f, m1 = -1e30f, l0 = 0.f, l1 = 0.f;
    const float scale = 0.17677669529663687f;
    const int colb = (lane & 3) << 1;

    for (int kt = 0; kt < kper; kt += 64) {
        __syncthreads();
#pragma unroll
        for (int i = 0; i < 2; i++) {
            int idx = tid + i*128;
            int row = idx >> 2, qt = idx & 3;
            int rk = min(kt + row, 511);
            const uint4 v = *(const uint4*)(g_qkvb + (base + rk) * 768 + 256 + hq + qt*8);
            *(uint4*)((char*)Ks + (row*QS + qt*8)*2) = v;
        }
#pragma unroll
        for (int i = 0; i < 4; i++) {
            int idx = tid + i*128;
            int key = idx >> 3, dg = (idx & 7) << 2;
            int rk = min(kt + key, 511);
            const uint2 v = *(const uint2*)(g_qkvb + (base + rk) * 768 + 512 + hq + dg);
            const __nv_bfloat16* pv = (const __nv_bfloat16*)&v;
            Vt[(dg+0)*VS + key] = pv[0];
            Vt[(dg+1)*VS + key] = pv[1];
            Vt[(dg+2)*VS + key] = pv[2];
            Vt[(dg+3)*VS + key] = pv[3];
        }
        __syncthreads();

        float cs[8][4];
#pragma unroll
        for (int nt = 0; nt < 8; nt++)
#pragma unroll
            for (int e = 0; e < 4; e++) cs[nt][e] = 0.f;
#pragma unroll
        for (int ks = 0; ks < 2; ks++) {
            uint32_t bk[8][2];
#pragma unroll
            for (int tp = 0; tp < 4; tp++) {
                uint32_t bd = ks_b + ((tp*16 + b_rw)*QS + ks*16 + b_kad)*2;
                ldsm4(bk[2*tp][0], bk[2*tp][1], bk[2*tp+1][0], bk[2*tp+1][1], bd);
            }
#pragma unroll
            for (int nt = 0; nt < 8; nt++)
                mma_bf16(cs[nt], aq[ks], bk[nt]);
        }
#pragma unroll
        for (int nt = 0; nt < 8; nt++) {
            int k0e = kt + nt*8 + colb;
#pragma unroll
            for (int e = 0; e < 4; e++) {
                float s = cs[nt][e] * scale;
                cs[nt][e] = (k0e + (e & 1) < kper) ? s : -1e30f;
            }
        }
        float mx0 = -1e30f, mx1 = -1e30f;
#pragma unroll
        for (int nt = 0; nt < 8; nt++) {
            mx0 = fmaxf(mx0, fmaxf(cs[nt][0], cs[nt][1]));
            mx1 = fmaxf(mx1, fmaxf(cs[nt][2], cs[nt][3]));
        }
        mx0 = fmaxf(mx0, __shfl_xor_sync(0xffffffffu, mx0, 1));
        mx0 = fmaxf(mx0, __shfl_xor_sync(0xffffffffu, mx0, 2));
        mx1 = fmaxf(mx1, __shfl_xor_sync(0xffffffffu, mx1, 1));
        mx1 = fmaxf(mx1, __shfl_xor_sync(0xffffffffu, mx1, 2));
        float mn0 = fmaxf(m0, mx0), mn1 = fmaxf(m1, mx1);
        float sf0 = __expf(m0 - mn0), sf1 = __expf(m1 - mn1);
        m0 = mn0; m1 = mn1;
        l0 *= sf0; l1 *= sf1;
#pragma unroll
        for (int nt = 0; nt < 4; nt++) {
            co[nt][0] *= sf0; co[nt][1] *= sf0;
            co[nt][2] *= sf1; co[nt][3] *= sf1;
        }
        uint32_t pa[4][4];
#pragma unroll
        for (int nt = 0; nt < 8; nt++) {
            float p0 = __expf(cs[nt][0] - m0);
            float p1 = __expf(cs[nt][1] - m0);
            float p2 = __expf(cs[nt][2] - m1);
            float p3 = __expf(cs[nt][3] - m1);
            l0 += p0 + p1; l1 += p2 + p3;
            int kc = nt >> 1, hi = (nt & 1) << 1;
            pa[kc][hi+0] = pk(p0, p1);
            pa[kc][hi+1] = pk(p2, p3);
        }
#pragma unroll
        for (int kc = 0; kc < 4; kc++) {
            uint32_t bv[4][2];
#pragma unroll
            for (int np = 0; np < 2; np++) {
                uint32_t vd = vt_b + ((np*16 + b_rw)*VS + kc*16 + b_kad)*2;
                ldsm4(bv[2*np][0], bv[2*np][1], bv[2*np+1][0], bv[2*np+1][1], vd);
            }
#pragma unroll
            for (int nt = 0; nt < 4; nt++)
                mma_bf16(co[nt], pa[kc], bv[nt]);
        }
    }
    l0 += __shfl_xor_sync(0xffffffffu, l0, 1);
    l0 += __shfl_xor_sync(0xffffffffu, l0, 2);
    l1 += __shfl_xor_sync(0xffffffffu, l1, 1);
    l1 += __shfl_xor_sync(0xffffffffu, l1, 2);
    float inv0 = 1.f / l0, inv1 = 1.f / l1;
    const int r0 = q0 + wid*16 + (lane >> 2);
#pragma unroll
    for (int nt = 0; nt < 4; nt++) {
        const int col = hq + nt*8 + colb;
        *(uint32_t*)(g_aob + (base + r0    ) * CC + col) = pk(co[nt][0]*inv0, co[nt][1]*inv0);
        *(uint32_t*)(g_aob + (base + r0 + 8) * CC + col) = pk(co[nt][2]*inv1, co[nt][3]*inv1);
    }
}

// ---------------- h = x * ratio (fp32 + bf16) ---------------------------------
__global__ __launch_bounds__(256)
void hbase_kernel(const float* __restrict__ x, const float* __restrict__ ratio)
{
    int i = blockIdx.x * 256 + threadIdx.x;   // float4 index
    int b = i >> 15;
    float r = ratio[b];
    float4 v = ((const float4*)x)[i];
    float4 o = make_float4(v.x*r, v.y*r, v.z*r, v.w*r);
    ((float4*)g_h)[i] = o;
    uint2 p; p.x = pk(o.x, o.y); p.y = pk(o.z, o.w);
    ((uint2*)g_hb)[i] = p;
}

// ------------------------------------------------------------------------------
extern "C" void kernel_launch(void* const* d_in, const int* in_sizes, int n_in,
                              void* d_out, int out_size)
{
    (void)in_sizes; (void)n_in; (void)out_size;
    const float* x      = (const float*)d_in[0];
    const float* ratio  = (const float*)d_in[3];
    const float* gumbel = (const float*)d_in[4];
    const float* Ws1    = (const float*)d_in[5];
    const float* bs1    = (const float*)d_in[6];
    const float* Ws2    = (const float*)d_in[7];
    const float* bs2    = (const float*)d_in[8];
    const float* Win    = (const float*)d_in[9];
    const float* b_in   = (const float*)d_in[10];
    const float* Wout   = (const float*)d_in[11];
    const float* bout   = (const float*)d_in[12];
    const float* Wm1    = (const float*)d_in[13];
    const float* bm1    = (const float*)d_in[14];
    const float* Wm2    = (const float*)d_in[15];
    const float* bm2    = (const float*)d_in[16];
    float* out = (float*)d_out;

    float *s1p, *hp;
    __nv_bfloat16 *qkvbp, *hcbp, *aobp, *hbp, *midbp, *winbp, *woutbp, *wm1bp, *wm2bp;
    cudaGetSymbolAddress((void**)&s1p,    g_s1);
    cudaGetSymbolAddress((void**)&hp,     g_h);
    cudaGetSymbolAddress((void**)&qkvbp,  g_qkvb);
    cudaGetSymbolAddress((void**)&hcbp,   g_hcb);
    cudaGetSymbolAddress((void**)&aobp,   g_aob);
    cudaGetSymbolAddress((void**)&hbp,    g_hb);
    cudaGetSymbolAddress((void**)&midbp,  g_midb);
    cudaGetSymbolAddress((void**)&winbp,  g_Winb);
    cudaGetSymbolAddress((void**)&woutbp, g_Woutb);
    cudaGetSymbolAddress((void**)&wm1bp,  g_Wm1b);
    cudaGetSymbolAddress((void**)&wm2bp,  g_Wm2b);

    // dynamic smem opt-in for the BK=64 GEMM (73728 B)
    cudaFuncSetAttribute(wmma_gemm<0,0,1,0>, cudaFuncAttributeMaxDynamicSharedMemorySize, GSMEM);
    cudaFuncSetAttribute(wmma_gemm<0,0,0,1>, cudaFuncAttributeMaxDynamicSharedMemorySize, GSMEM);
    cudaFuncSetAttribute(wmma_gemm<1,0,1,0>, cudaFuncAttributeMaxDynamicSharedMemorySize, GSMEM);
    cudaFuncSetAttribute(wmma_gemm<0,1,0,0>, cudaFuncAttributeMaxDynamicSharedMemorySize, GSMEM);

    // weight conversions (single launch, 4 segments)
    f2bf4_kernel<<<512, 256>>>(Win, winbp, Wout, woutbp, Wm1, wm1bp, Wm2, wm2bp);

    // 1. scorer (fp32 — bit-faithful selection path, do not touch)
    gemm_kernel<1><<<dim3(CC/128, NTOK/128), 256>>>(x, Ws1, bs1, s1p, NTOK, CC, CC);
    score_kernel<<<NTOK/8, 256>>>(Ws2, bs2);
    softmax_kernel<<<BB, 512>>>(gumbel);
    kper_kernel<<<1, 64>>>(ratio);
    topk_kernel<<<BB, 512>>>();
    // 2. gather (bf16) + h base (must precede fused Wout-scatter)
    gather_kernel<<<NTOK/4, 256>>>(x);
    hbase_kernel<<<(NTOK*CC/4)/256, 256>>>(x, ratio);
    // 3. qkv = h_compact @ Win^T + b_in  (HMMA, bf16 out)
    wmma_gemm<0,0,1,0><<<dim3(6, NTOK/128), 256, GSMEM>>>(hcbp, winbp, b_in, nullptr,
                                                   nullptr, qkvbp, nullptr, NTOK, 3*CC, CC);
    // 4. attention (HMMA flash-attn, bf16 out)
    attn_mma_kernel<<<dim3(BB*HH, 8), 128>>>();
    // 5. Wout GEMM with fused scatter: h[topk] = (ao@Wout^T + bout + x)*ratio
    wmma_gemm<0,0,0,1><<<dim3(2, NTOK/128), 256, GSMEM>>>(aobp, woutbp, bout, x,
                                                   nullptr, nullptr, ratio, NTOK, CC, CC);
    // 6. mid = relu(h @ Wm1^T + bm1)  (bf16 out)
    wmma_gemm<1,0,1,0><<<dim3(4, NTOK/128), 256, GSMEM>>>(hbp, wm1bp, bm1, nullptr,
                                                   nullptr, midbp, nullptr, NTOK, 2*CC, CC);
    // 7. out = h + mid @ Wm2^T + bm2
    wmma_gemm<0,1,0,0><<<dim3(2, NTOK/128), 256, GSMEM>>>(midbp, wm2bp, bm2, hp,
                                                   out, nullptr, nullptr, NTOK, CC, 2*CC);
}

// round 16
// speedup vs baseline: 1.1128x; 1.1128x over previous
#include <cuda_runtime.h>
#include <cuda_bf16.h>
#include <math.h>
#include <stdint.h>

#define BB   64
#define LL   512
#define CC   256
#define HH   8
#define DHH  32
#define NTOK (BB*LL)

// ---------------- scratch (static __device__, no allocations) ----------------
__device__ float g_zpart[2*NTOK];             // scorer partial dots (cols 0-127 / 128-255)
__device__ float g_sv[BB*LL];                 // y_soft values (jax-replicated)
__device__ unsigned char g_tier2[BB*LL];      // token_mask residue flag
__device__ int   g_kper[BB];
__device__ int   g_kmax;
__device__ int   g_topk[BB*LL];
__device__ float g_h[(size_t)NTOK*CC];        // fp32 residual-scaled hidden
// bf16 operands for tensor-core GEMMs / attention
__device__ __nv_bfloat16 g_qkvb[(size_t)NTOK*3*CC];
__device__ __nv_bfloat16 g_hcb [(size_t)NTOK*CC];
__device__ __nv_bfloat16 g_aob [(size_t)NTOK*CC];
__device__ __nv_bfloat16 g_hb  [(size_t)NTOK*CC];
__device__ __nv_bfloat16 g_midb[(size_t)NTOK*2*CC];
__device__ __nv_bfloat16 g_Winb [3*CC*CC];
__device__ __nv_bfloat16 g_Woutb[CC*CC];
__device__ __nv_bfloat16 g_Wm1b [2*CC*CC];
__device__ __nv_bfloat16 g_Wm2b [CC*2*CC];

// ---------------- helpers -----------------------------------------------------
__device__ __forceinline__ uint32_t smem_u32(const void* p){
    uint32_t a;
    asm("{ .reg .u64 t; cvta.to.shared.u64 t, %1; cvt.u32.u64 %0, t; }" : "=r"(a) : "l"(p));
    return a;
}
__device__ __forceinline__ uint32_t pk(float a, float b){
    __nv_bfloat162 t = __floats2bfloat162_rn(a, b);
    return *reinterpret_cast<uint32_t*>(&t);
}
__device__ __forceinline__ void ldsm4(uint32_t& r0, uint32_t& r1, uint32_t& r2, uint32_t& r3,
                                      uint32_t addr){
    asm volatile("ldmatrix.sync.aligned.m8n8.x4.shared.b16 {%0,%1,%2,%3}, [%4];"
                 : "=r"(r0), "=r"(r1), "=r"(r2), "=r"(r3) : "r"(addr));
}
__device__ __forceinline__ void mma_bf16(float* c, const uint32_t* a, const uint32_t* b){
    asm volatile("mma.sync.aligned.m16n8k16.row.col.f32.bf16.bf16.f32 "
                 "{%0,%1,%2,%3}, {%4,%5,%6,%7}, {%8,%9}, {%0,%1,%2,%3};"
                 : "+f"(c[0]), "+f"(c[1]), "+f"(c[2]), "+f"(c[3])
                 : "r"(a[0]), "r"(a[1]), "r"(a[2]), "r"(a[3]), "r"(b[0]), "r"(b[1]));
}
__device__ __forceinline__ void cp16(uint32_t dst, const void* src){
    asm volatile("cp.async.cg.shared.global [%0], [%1], 16;" :: "r"(dst), "l"(src) : "memory");
}
#define CP_COMMIT() asm volatile("cp.async.commit_group;" ::: "memory")
#define CP_WAIT0()  asm volatile("cp.async.wait_group 0;"  ::: "memory")
__device__ __forceinline__ void ffma2(uint64_t& c, uint64_t a, uint64_t b){
    asm volatile("fma.rn.f32x2 %0, %1, %2, %0;" : "+l"(c) : "l"(a), "l"(b));
}
__device__ __forceinline__ uint64_t pk64(float lo, float hi){
    uint64_t v;
    asm("mov.b64 %0, {%1, %2};" : "=l"(v) : "f"(lo), "f"(hi));
    return v;
}
__device__ __forceinline__ void unpk64(float& lo, float& hi, uint64_t v){
    asm("mov.b64 {%0, %1}, %2;" : "=f"(lo), "=f"(hi) : "l"(v));
}

// ---------------- warp-MMA bf16 GEMM (R14 config: BK=32, 2-stage, static smem) -
#define SROW 40                      // smem row stride in bf16 (padded, 80B)
#define STAGEB (128*SROW*2)          // stage size in bytes (10240)

template<int ACT, int RES, int OUTBF, int SCAT>
__global__ __launch_bounds__(256)
void wmma_gemm(const __nv_bfloat16* __restrict__ A, const __nv_bfloat16* __restrict__ W,
               const float* __restrict__ bias, const float* __restrict__ res,
               float* __restrict__ outf, __nv_bfloat16* __restrict__ outb,
               const float* __restrict__ ratio,
               int M, int N, int K)
{
    __shared__ __align__(16) __nv_bfloat16 As[2*128*SROW];
    __shared__ __align__(16) __nv_bfloat16 Bs[2*128*SROW];
    const uint32_t as_b = smem_u32(As);
    const uint32_t bs_b = smem_u32(Bs);
    const int tid  = threadIdx.x;
    const int wid  = tid >> 5, lane = tid & 31;
    const int bm   = blockIdx.y << 7;
    const int bn   = blockIdx.x << 7;
    const int wm   = wid & 3;
    const int wn   = wid >> 2;

    const int lrow0 = (tid >> 2);
    const int lch   = (tid & 3) << 3;
    const __nv_bfloat16* Ap0 = A + (size_t)(bm + lrow0     ) * K + lch;
    const __nv_bfloat16* Ap1 = A + (size_t)(bm + lrow0 + 64) * K + lch;
    const __nv_bfloat16* Wp0 = W + (size_t)(bn + lrow0     ) * K + lch;
    const __nv_bfloat16* Wp1 = W + (size_t)(bn + lrow0 + 64) * K + lch;
    const uint32_t soff0 = (uint32_t)(lrow0      * SROW + lch) * 2;
    const uint32_t soff1 = (uint32_t)((lrow0+64) * SROW + lch) * 2;

    const uint32_t a_row = (uint32_t)(wm*32 + (lane & 15));
    const uint32_t a_kad = (uint32_t)((lane >> 4) << 3);
    const uint32_t b_row = (uint32_t)(wn*64 + ((lane >> 4) << 3) + (lane & 7));
    const uint32_t b_kad = (uint32_t)(((lane >> 3) & 1) << 3);

    float acc[2][8][4];
#pragma unroll
    for (int i = 0; i < 2; i++)
#pragma unroll
        for (int j = 0; j < 8; j++)
#pragma unroll
            for (int q = 0; q < 4; q++) acc[i][j][q] = 0.f;

    const int nc = K >> 5;
    {
        cp16(as_b + soff0, Ap0); cp16(as_b + soff1, Ap1);
        cp16(bs_b + soff0, Wp0); cp16(bs_b + soff1, Wp1);
        CP_COMMIT();
    }

    for (int c = 0; c < nc; c++) {
        CP_WAIT0();
        __syncthreads();
        if (c + 1 < nc) {
            const int k1 = (c + 1) << 5;
            const uint32_t sb = ((c + 1) & 1) * STAGEB;
            cp16(as_b + sb + soff0, Ap0 + k1); cp16(as_b + sb + soff1, Ap1 + k1);
            cp16(bs_b + sb + soff0, Wp0 + k1); cp16(bs_b + sb + soff1, Wp1 + k1);
            CP_COMMIT();
        }
        const uint32_t ab = as_b + (c & 1) * STAGEB;
        const uint32_t bb = bs_b + (c & 1) * STAGEB;
#pragma unroll
        for (int ks = 0; ks < 2; ks++) {
            const uint32_t kcol = (uint32_t)(ks << 4);
            uint32_t a[2][4];
#pragma unroll
            for (int tm = 0; tm < 2; tm++) {
                uint32_t ad = ab + ((a_row + tm*16) * SROW + kcol + a_kad) * 2;
                ldsm4(a[tm][0], a[tm][1], a[tm][2], a[tm][3], ad);
            }
            uint32_t b[8][2];
#pragma unroll
            for (int tp = 0; tp < 4; tp++) {
                uint32_t bd = bb + ((b_row + tp*16) * SROW + kcol + b_kad) * 2;
                ldsm4(b[2*tp][0], b[2*tp][1], b[2*tp+1][0], b[2*tp+1][1], bd);
            }
#pragma unroll
            for (int tm = 0; tm < 2; tm++)
#pragma unroll
                for (int tn = 0; tn < 8; tn++)
                    mma_bf16(acc[tm][tn], a[tm], b[tn]);
        }
        __syncthreads();
    }

    if (SCAT) {
        const int kmax = g_kmax;
#pragma unroll
        for (int tm = 0; tm < 2; tm++) {
#pragma unroll
            for (int half = 0; half < 2; half++) {
                const int m = bm + wm*32 + tm*16 + (lane >> 2) + half*8;
                const int b = m >> 9, j = m & 511;
                if (j >= kmax) continue;
                const int dst = g_topk[m];
                const size_t node = (((size_t)b << 9) + dst) * CC;
                const float r = ratio[b];
#pragma unroll
                for (int tn = 0; tn < 8; tn++) {
                    const int gn = bn + wn*64 + tn*8 + ((lane & 3) << 1);
                    float v0 = acc[tm][tn][2*half+0] + bias[gn];
                    float v1 = acc[tm][tn][2*half+1] + bias[gn+1];
                    float2 xv = *(const float2*)(res + node + gn);
                    v0 = (v0 + xv.x) * r;
                    v1 = (v1 + xv.y) * r;
                    *(float2*)(g_h + node + gn) = make_float2(v0, v1);
                    *(uint32_t*)(g_hb + node + gn) = pk(v0, v1);
                }
            }
        }
        return;
    }

#pragma unroll
    for (int tm = 0; tm < 2; tm++) {
        const int gm = bm + wm*32 + tm*16 + (lane >> 2);
#pragma unroll
        for (int tn = 0; tn < 8; tn++) {
            const int gn = bn + wn*64 + tn*8 + ((lane & 3) << 1);
            const float b0 = bias[gn], b1 = bias[gn+1];
#pragma unroll
            for (int half = 0; half < 2; half++) {
                const int m = gm + half*8;
                float v0 = acc[tm][tn][2*half+0] + b0;
                float v1 = acc[tm][tn][2*half+1] + b1;
                if (ACT) { v0 = fmaxf(v0, 0.f); v1 = fmaxf(v1, 0.f); }
                const size_t o = (size_t)m * N + gn;
                if (RES) {
                    float2 r = *(const float2*)(res + o);
                    v0 += r.x; v1 += r.y;
                }
                if (OUTBF) *(uint32_t*)(outb + o) = pk(v0, v1);
                else       *(float2*)(outf + o)   = make_float2(v0, v1);
            }
        }
    }
}

// ---------------- scorer GEMM with fused score dot ----------------------------
// s1_tile = relu(x@Ws1^T + bs1) (in regs); zpart[bx][m] = s1_tile[m,:]·Ws2[bn:bn+128]
__global__ __launch_bounds__(256)
void scorer_gemm(const float* __restrict__ A, const float* __restrict__ W,
                 const float* __restrict__ bias, const float* __restrict__ Ws2,
                 int M, int K)
{
    __shared__ float As[8][132];
    __shared__ float Bs[8][132];
    const int tid = threadIdx.x;
    const int tx = tid & 15, ty = tid >> 4;
    const int bm = blockIdx.y << 7, bn = blockIdx.x << 7;
    const int lr = tid >> 1;
    const int lc = (tid & 1) << 2;

    uint64_t acc2[8][4];
#pragma unroll
    for (int i = 0; i < 8; i++)
#pragma unroll
        for (int j = 0; j < 4; j++) acc2[i][j] = 0ull;

    const float* Ap = A + (size_t)(bm + lr) * K + lc;
    const float* Wp = W + (size_t)(bn + lr) * K + lc;

    float4 av = *(const float4*)Ap;
    float4 wv = *(const float4*)Wp;

    for (int k0 = 0; k0 < K; k0 += 8) {
        __syncthreads();
        As[lc+0][lr]=av.x; As[lc+1][lr]=av.y; As[lc+2][lr]=av.z; As[lc+3][lr]=av.w;
        Bs[lc+0][lr]=wv.x; Bs[lc+1][lr]=wv.y; Bs[lc+2][lr]=wv.z; Bs[lc+3][lr]=wv.w;
        __syncthreads();
        if (k0 + 8 < K) {
            av = *(const float4*)(Ap + k0 + 8);
            wv = *(const float4*)(Wp + k0 + 8);
        }
#pragma unroll
        for (int kk = 0; kk < 8; kk++) {
            float a[8], b[8];
            *(float4*)&a[0] = *(const float4*)&As[kk][ty*8];
            *(float4*)&a[4] = *(const float4*)&As[kk][ty*8+4];
            *(float4*)&b[0] = *(const float4*)&Bs[kk][tx*8];
            *(float4*)&b[4] = *(const float4*)&Bs[kk][tx*8+4];
            uint64_t bp[4];
#pragma unroll
            for (int j = 0; j < 4; j++) bp[j] = pk64(b[2*j], b[2*j+1]);
#pragma unroll
            for (int i = 0; i < 8; i++) {
                const uint64_t ad = pk64(a[i], a[i]);
#pragma unroll
                for (int j = 0; j < 4; j++)
                    ffma2(acc2[i][j], ad, bp[j]);
            }
        }
    }

    // fused epilogue: bias + relu + row-dot with Ws2, deterministic order
    const int nb = bn + tx*8;
    float w2[8];
#pragma unroll
    for (int j = 0; j < 8; j++) w2[j] = Ws2[nb + j];
    const float bi[8] = { bias[nb], bias[nb+1], bias[nb+2], bias[nb+3],
                          bias[nb+4], bias[nb+5], bias[nb+6], bias[nb+7] };

    float rowp[8];
#pragma unroll
    for (int i = 0; i < 8; i++) {
        float v[8];
        unpk64(v[0], v[1], acc2[i][0]);
        unpk64(v[2], v[3], acc2[i][1]);
        unpk64(v[4], v[5], acc2[i][2]);
        unpk64(v[6], v[7], acc2[i][3]);
        float p = 0.f;
#pragma unroll
        for (int j = 0; j < 8; j++)
            p = fmaf(fmaxf(v[j] + bi[j], 0.f), w2[j], p);
        rowp[i] = p;
    }
    // reduce across the 16 tx threads (xor tree within 16-lane halves)
#pragma unroll
    for (int i = 0; i < 8; i++) {
#pragma unroll
        for (int off = 8; off; off >>= 1)
            rowp[i] += __shfl_xor_sync(0xffffffffu, rowp[i], off);
    }
    if (tx == 0) {
        const int mbase = bm + ty*8;
#pragma unroll
        for (int i = 0; i < 8; i++)
            g_zpart[blockIdx.x * NTOK + mbase + i] = rowp[i];
    }
}

// ---------------- weights fp32->bf16 (4 segs) + kper/kmax (block 512) ---------
__global__ __launch_bounds__(256)
void f2bf4_kernel(const float* __restrict__ Win,  __nv_bfloat16* __restrict__ dWin,
                  const float* __restrict__ Wout, __nv_bfloat16* __restrict__ dWout,
                  const float* __restrict__ Wm1,  __nv_bfloat16* __restrict__ dWm1,
                  const float* __restrict__ Wm2,  __nv_bfloat16* __restrict__ dWm2,
                  const float* __restrict__ ratio)
{
    int blk = blockIdx.x;
    if (blk == 512) {
        __shared__ int sm[64];
        int t = threadIdx.x;
        if (t < 64) {
            int kp = (int)ceilf(ratio[t] * 512.0f);
            if (kp < 1)  kp = 1;
            if (kp > LL) kp = LL;
            g_kper[t] = kp;
            sm[t] = kp;
        }
        __syncthreads();
        for (int s = 32; s > 0; s >>= 1) {
            if (t < s) sm[t] = max(sm[t], sm[t+s]);
            __syncthreads();
        }
        if (t == 0) g_kmax = sm[0];
        return;
    }
    const float* s; __nv_bfloat16* d; int off;
    if      (blk < 192) { s = Win;  d = dWin;  off = blk;       }
    else if (blk < 256) { s = Wout; d = dWout; off = blk - 192; }
    else if (blk < 384) { s = Wm1;  d = dWm1;  off = blk - 256; }
    else                { s = Wm2;  d = dWm2;  off = blk - 384; }
    int i = off * 256 + threadIdx.x;
    float4 v = ((const float4*)s)[i];
    uint2 p; p.x = pk(v.x, v.y); p.y = pk(v.z, v.w);
    ((uint2*)d)[i] = p;
}

// ---------------- jax-replicated softmax pipeline + tier flag -----------------
__global__ __launch_bounds__(512)
void softmax_kernel(const float* __restrict__ gumbel, const float* __restrict__ bs2)
{
    __shared__ float red[512];
    const int b = blockIdx.x, t = threadIdx.x;
    const int n = b * 512 + t;
    float sc = __fadd_rn(__fadd_rn(g_zpart[n], g_zpart[NTOK + n]), bs2[0]);

    red[t] = sc; __syncthreads();
#pragma unroll
    for (int s = 256; s; s >>= 1) { if (t < s) red[t] = fmaxf(red[t], red[t+s]); __syncthreads(); }
    float m1 = red[0]; __syncthreads();

    float sh = __fadd_rn(sc, -m1);
    float e1 = expf(sh);
    red[t] = e1; __syncthreads();
#pragma unroll
    for (int s = 256; s; s >>= 1) { if (t < s) red[t] = __fadd_rn(red[t], red[t+s]); __syncthreads(); }
    float L = logf(red[0]); __syncthreads();

    float ls = __fadd_rn(sh, -L);
    float z  = __fadd_rn(ls, gumbel[n]);
    red[t] = z; __syncthreads();
#pragma unroll
    for (int s = 256; s; s >>= 1) { if (t < s) red[t] = fmaxf(red[t], red[t+s]); __syncthreads(); }
    float m2 = red[0]; __syncthreads();

    float e2 = expf(__fadd_rn(z, -m2));
    red[t] = e2; __syncthreads();
#pragma unroll
    for (int s = 256; s; s >>= 1) { if (t < s) red[t] = __fadd_rn(red[t], red[t+s]); __syncthreads(); }
    float S = red[0];

    float sval = __fdiv_rn(e2, S);
    g_sv[n] = sval;
    float tt = __fadd_rn(__fadd_rn(1.0f, sval), -sval);
    g_tier2[n] = (tt != 1.0f) ? 1 : 0;
}

// ---------------- per-batch selection (tier-aware, replicates reference) ------
__global__ __launch_bounds__(512)
void topk_kernel()
{
    __shared__ float sv[512];
    __shared__ int   si[512];
    __shared__ int   sfl[512];
    __shared__ int   sA[512];
    const int b = blockIdx.x, t = threadIdx.x;
    sv[t] = g_sv[b*512 + t];
    si[t] = t;
    __syncthreads();
    for (int k = 2; k <= 512; k <<= 1) {
        for (int j = k >> 1; j > 0; j >>= 1) {
            int ixj = t ^ j;
            if (ixj > t) {
                bool desc = ((t & k) == 0);
                float v1 = sv[t], v2 = sv[ixj];
                int   i1 = si[t], i2 = si[ixj];
                bool less = (v1 < v2) || (v1 == v2 && i1 > i2);
                bool sw = desc ? less : !less;
                if (sw) {
                    sv[t] = v2; sv[ixj] = v1;
                    si[t] = i2; si[ixj] = i1;
                }
            }
            __syncthreads();
        }
    }
    const int kmax = g_kmax;
    const int kper = g_kper[b];
    sfl[si[t]] = (t < kmax) ? 1 : 0;
    __syncthreads();
    const int sel   = sfl[t];
    const int tier2 = (int)g_tier2[b*512 + t];
    const int a1 = sel & (tier2 ^ 1);
    const int a2 = sel & tier2;
    sA[t] = a1 | (a2 << 16);
    __syncthreads();
    for (int off = 1; off < 512; off <<= 1) {
        int add = (t >= off) ? sA[t-off] : 0;
        __syncthreads();
        sA[t] += add;
        __syncthreads();
    }
    const int inc1 = sA[t] & 0xffff, inc2 = sA[t] >> 16;
    const int n1   = sA[511] & 0xffff;
    const int excl1 = inc1 - a1, excl2 = inc2 - a2;
    const int kept = (a1 && excl1 < kper) || (a2 && (n1 + excl2) < kper);
    const int nk = 1 - kept;
    __syncthreads();
    sA[t] = kept | (nk << 16);
    __syncthreads();
    for (int off = 1; off < 512; off <<= 1) {
        int add = (t >= off) ? sA[t-off] : 0;
        __syncthreads();
        sA[t] += add;
        __syncthreads();
    }
    const int rk = (sA[t] & 0xffff) - kept;
    const int rn = (sA[t] >> 16) - nk;
    if (kept) g_topk[b*512 + rk] = t;
    else      g_topk[b*512 + kper + rn] = t;
}

// ---------------- gather (blocks [0, NTOK/4)) + hbase (rest) ------------------
__global__ __launch_bounds__(256)
void gather_hbase_kernel(const float* __restrict__ x, const float* __restrict__ ratio)
{
    const int blk = blockIdx.x;
    if (blk < NTOK/4) {
        int row = blk * 4 + (threadIdx.x >> 6);
        int b = row >> 9, j = row & 511;
        int t = threadIdx.x & 63;
        uint2* dst = (uint2*)(g_hcb + (size_t)row * CC);
        if (j < g_kper[b]) {
            int src = g_topk[row];
            float4 v = ((const float4*)(x + ((size_t)b*512 + src) * CC))[t];
            uint2 o; o.x = pk(v.x, v.y); o.y = pk(v.z, v.w);
            dst[t] = o;
        } else {
            dst[t] = make_uint2(0u, 0u);
        }
    } else {
        int i = (blk - NTOK/4) * 256 + threadIdx.x;   // float4 index
        int b = i >> 15;
        float r = ratio[b];
        float4 v = ((const float4*)x)[i];
        float4 o = make_float4(v.x*r, v.y*r, v.z*r, v.w*r);
        ((float4*)g_h)[i] = o;
        uint2 p; p.x = pk(o.x, o.y); p.y = pk(o.z, o.w);
        ((uint2*)g_hb)[i] = p;
    }
}

// ---------------- flash attention v2 on HMMA (bf16 in, fp32 accum) ------------
#define QS 40   // Q/K smem stride (bf16)
#define VS 72   // Vt smem stride (bf16)
__global__ __launch_bounds__(128)
void attn_mma_kernel()
{
    __shared__ __align__(16) __nv_bfloat16 Qs[64*QS];
    __shared__ __align__(16) __nv_bfloat16 Ks[64*QS];
    __shared__ __align__(16) __nv_bfloat16 Vt[32*VS];
    const uint32_t qs_b = smem_u32(Qs);
    const uint32_t ks_b = smem_u32(Ks);
    const uint32_t vt_b = smem_u32(Vt);

    const int bh = blockIdx.x;
    const int b = bh >> 3, h = bh & 7;
    const int q0 = blockIdx.y << 6;
    const int tid = threadIdx.x;
    const int wid = tid >> 5, lane = tid & 31;
    const int kper = g_kper[b];
    const size_t base = (size_t)b * 512;
    const int hq = h * 32;

#pragma unroll
    for (int i = 0; i < 2; i++) {
        int idx = tid + i*128;
        int row = idx >> 2, qt = idx & 3;
        const uint4 v = *(const uint4*)(g_qkvb + (base + q0 + row) * 768 + hq + qt*8);
        *(uint4*)((char*)Qs + (row*QS + qt*8)*2) = v;
    }

    const uint32_t a_row = (uint32_t)(wid*16 + (lane & 15));
    const uint32_t a_kad = (uint32_t)((lane >> 4) << 3);
    const uint32_t b_rw  = (uint32_t)(((lane >> 4) << 3) + (lane & 7));
    const uint32_t b_kad = (uint32_t)(((lane >> 3) & 1) << 3);
    __syncthreads();
    uint32_t aq[2][4];
#pragma unroll
    for (int ks = 0; ks < 2; ks++)
        ldsm4(aq[ks][0], aq[ks][1], aq[ks][2], aq[ks][3],
              qs_b + (a_row*QS + ks*16 + a_kad)*2);

    float co[4][4];
#pragma unroll
    for (int i = 0; i < 4; i++)
#pragma unroll
        for (int j = 0; j < 4; j++) co[i][j] = 0.f;
    float m0 = -1e30f, m1 = -1e30f, l0 = 0.f, l1 = 0.f;
    const float scale = 0.17677669529663687f;
    const int colb = (lane & 3) << 1;

    for (int kt = 0; kt < kper; kt += 64) {
        __syncthreads();
#pragma unroll
        for (int i = 0; i < 2; i++) {
            int idx = tid + i*128;
            int row = idx >> 2, qt = idx & 3;
            int rk = min(kt + row, 511);
            const uint4 v = *(const uint4*)(g_qkvb + (base + rk) * 768 + 256 + hq + qt*8);
            *(uint4*)((char*)Ks + (row*QS + qt*8)*2) = v;
        }
#pragma unroll
        for (int i = 0; i < 4; i++) {
            int idx = tid + i*128;
            int key = idx >> 3, dg = (idx & 7) << 2;
            int rk = min(kt + key, 511);
            const uint2 v = *(const uint2*)(g_qkvb + (base + rk) * 768 + 512 + hq + dg);
            const __nv_bfloat16* pv = (const __nv_bfloat16*)&v;
            Vt[(dg+0)*VS + key] = pv[0];
            Vt[(dg+1)*VS + key] = pv[1];
            Vt[(dg+2)*VS + key] = pv[2];
            Vt[(dg+3)*VS + key] = pv[3];
        }
        __syncthreads();

        float cs[8][4];
#pragma unroll
        for (int nt = 0; nt < 8; nt++)
#pragma unroll
            for (int e = 0; e < 4; e++) cs[nt][e] = 0.f;
#pragma unroll
        for (int ks = 0; ks < 2; ks++) {
            uint32_t bk[8][2];
#pragma unroll
            for (int tp = 0; tp < 4; tp++) {
                uint32_t bd = ks_b + ((tp*16 + b_rw)*QS + ks*16 + b_kad)*2;
                ldsm4(bk[2*tp][0], bk[2*tp][1], bk[2*tp+1][0], bk[2*tp+1][1], bd);
            }
#pragma unroll
            for (int nt = 0; nt < 8; nt++)
                mma_bf16(cs[nt], aq[ks], bk[nt]);
        }
#pragma unroll
        for (int nt = 0; nt < 8; nt++) {
            int k0e = kt + nt*8 + colb;
#pragma unroll
            for (int e = 0; e < 4; e++) {
                float s = cs[nt][e] * scale;
                cs[nt][e] = (k0e + (e & 1) < kper) ? s : -1e30f;
            }
        }
        float mx0 = -1e30f, mx1 = -1e30f;
#pragma unroll
        for (int nt = 0; nt < 8; nt++) {
            mx0 = fmaxf(mx0, fmaxf(cs[nt][0], cs[nt][1]));
            mx1 = fmaxf(mx1, fmaxf(cs[nt][2], cs[nt][3]));
        }
        mx0 = fmaxf(mx0, __shfl_xor_sync(0xffffffffu, mx0, 1));
        mx0 = fmaxf(mx0, __shfl_xor_sync(0xffffffffu, mx0, 2));
        mx1 = fmaxf(mx1, __shfl_xor_sync(0xffffffffu, mx1, 1));
        mx1 = fmaxf(mx1, __shfl_xor_sync(0xffffffffu, mx1, 2));
        float mn0 = fmaxf(m0, mx0), mn1 = fmaxf(m1, mx1);
        float sf0 = __expf(m0 - mn0), sf1 = __expf(m1 - mn1);
        m0 = mn0; m1 = mn1;
        l0 *= sf0; l1 *= sf1;
#pragma unroll
        for (int nt = 0; nt < 4; nt++) {
            co[nt][0] *= sf0; co[nt][1] *= sf0;
            co[nt][2] *= sf1; co[nt][3] *= sf1;
        }
        uint32_t pa[4][4];
#pragma unroll
        for (int nt = 0; nt < 8; nt++) {
            float p0 = __expf(cs[nt][0] - m0);
            float p1 = __expf(cs[nt][1] - m0);
            float p2 = __expf(cs[nt][2] - m1);
            float p3 = __expf(cs[nt][3] - m1);
            l0 += p0 + p1; l1 += p2 + p3;
            int kc = nt >> 1, hi = (nt & 1) << 1;
            pa[kc][hi+0] = pk(p0, p1);
            pa[kc][hi+1] = pk(p2, p3);
        }
#pragma unroll
        for (int kc = 0; kc < 4; kc++) {
            uint32_t bv[4][2];
#pragma unroll
            for (int np = 0; np < 2; np++) {
                uint32_t vd = vt_b + ((np*16 + b_rw)*VS + kc*16 + b_kad)*2;
                ldsm4(bv[2*np][0], bv[2*np][1], bv[2*np+1][0], bv[2*np+1][1], vd);
            }
#pragma unroll
            for (int nt = 0; nt < 4; nt++)
                mma_bf16(co[nt], pa[kc], bv[nt]);
        }
    }
    l0 += __shfl_xor_sync(0xffffffffu, l0, 1);
    l0 += __shfl_xor_sync(0xffffffffu, l0, 2);
    l1 += __shfl_xor_sync(0xffffffffu, l1, 1);
    l1 += __shfl_xor_sync(0xffffffffu, l1, 2);
    float inv0 = 1.f / l0, inv1 = 1.f / l1;
    const int r0 = q0 + wid*16 + (lane >> 2);
#pragma unroll
    for (int nt = 0; nt < 4; nt++) {
        const int col = hq + nt*8 + colb;
        *(uint32_t*)(g_aob + (base + r0    ) * CC + col) = pk(co[nt][0]*inv0, co[nt][1]*inv0);
        *(uint32_t*)(g_aob + (base + r0 + 8) * CC + col) = pk(co[nt][2]*inv1, co[nt][3]*inv1);
    }
}

// ------------------------------------------------------------------------------
extern "C" void kernel_launch(void* const* d_in, const int* in_sizes, int n_in,
                              void* d_out, int out_size)
{
    (void)in_sizes; (void)n_in; (void)out_size;
    const float* x      = (const float*)d_in[0];
    const float* ratio  = (const float*)d_in[3];
    const float* gumbel = (const float*)d_in[4];
    const float* Ws1    = (const float*)d_in[5];
    const float* bs1    = (const float*)d_in[6];
    const float* Ws2    = (const float*)d_in[7];
    const float* bs2    = (const float*)d_in[8];
    const float* Win    = (const float*)d_in[9];
    const float* b_in   = (const float*)d_in[10];
    const float* Wout   = (const float*)d_in[11];
    const float* bout   = (const float*)d_in[12];
    const float* Wm1    = (const float*)d_in[13];
    const float* bm1    = (const float*)d_in[14];
    const float* Wm2    = (const float*)d_in[15];
    const float* bm2    = (const float*)d_in[16];
    float* out = (float*)d_out;

    float *hp;
    __nv_bfloat16 *qkvbp, *hcbp, *aobp, *hbp, *midbp, *winbp, *woutbp, *wm1bp, *wm2bp;
    cudaGetSymbolAddress((void**)&hp,     g_h);
    cudaGetSymbolAddress((void**)&qkvbp,  g_qkvb);
    cudaGetSymbolAddress((void**)&hcbp,   g_hcb);
    cudaGetSymbolAddress((void**)&aobp,   g_aob);
    cudaGetSymbolAddress((void**)&hbp,    g_hb);
    cudaGetSymbolAddress((void**)&midbp,  g_midb);
    cudaGetSymbolAddress((void**)&winbp,  g_Winb);
    cudaGetSymbolAddress((void**)&woutbp, g_Woutb);
    cudaGetSymbolAddress((void**)&wm1bp,  g_Wm1b);
    cudaGetSymbolAddress((void**)&wm2bp,  g_Wm2b);

    // weight conversions + kper/kmax (single launch)
    f2bf4_kernel<<<513, 256>>>(Win, winbp, Wout, woutbp, Wm1, wm1bp, Wm2, wm2bp, ratio);

    // 1. scorer GEMM with fused score dot -> g_zpart
    scorer_gemm<<<dim3(CC/128, NTOK/128), 256>>>(x, Ws1, bs1, Ws2, NTOK, CC);
    softmax_kernel<<<BB, 512>>>(gumbel, bs2);
    topk_kernel<<<BB, 512>>>();
    // 2. gather (bf16) + h base (fused; must precede Wout-scatter)
    gather_hbase_kernel<<<NTOK/4 + (NTOK*CC/4)/256, 256>>>(x, ratio);
    // 3. qkv = h_compact @ Win^T + b_in  (HMMA, bf16 out)
    wmma_gemm<0,0,1,0><<<dim3(6, NTOK/128), 256>>>(hcbp, winbp, b_in, nullptr,
                                                   nullptr, qkvbp, nullptr, NTOK, 3*CC, CC);
    // 4. attention (HMMA flash-attn, bf16 out)
    attn_mma_kernel<<<dim3(BB*HH, 8), 128>>>();
    // 5. Wout GEMM with fused scatter: h[topk] = (ao@Wout^T + bout + x)*ratio
    wmma_gemm<0,0,0,1><<<dim3(2, NTOK/128), 256>>>(aobp, woutbp, bout, x,
                                                   nullptr, nullptr, ratio, NTOK, CC, CC);
    // 6. mid = relu(h @ Wm1^T + bm1)  (bf16 out)
    wmma_gemm<1,0,1,0><<<dim3(4, NTOK/128), 256>>>(hbp, wm1bp, bm1, nullptr,
                                                   nullptr, midbp, nullptr, NTOK, 2*CC, CC);
    // 7. out = h + mid @ Wm2^T + bm2
    wmma_gemm<0,1,0,0><<<dim3(2, NTOK/128), 256>>>(midbp, wm2bp, bm2, hp,
                                                   out, nullptr, nullptr, NTOK, CC, 2*CC);
}

// round 17
// speedup vs baseline: 1.1604x; 1.0427x over previous
#include <cuda_runtime.h>
#include <cuda_bf16.h>
#include <math.h>
#include <stdint.h>

#define BB   64
#define LL   512
#define CC   256
#define HH   8
#define DHH  32
#define NTOK (BB*LL)

// ---------------- scratch (static __device__, no allocations) ----------------
__device__ float g_zpart[2*NTOK];             // scorer partial dots (cols 0-127 / 128-255)
__device__ float g_sv[BB*LL];                 // y_soft values (jax-replicated)
__device__ unsigned char g_tier2[BB*LL];      // token_mask residue flag
__device__ int   g_kper[BB];
__device__ int   g_kmax;
__device__ int   g_topk[BB*LL];
__device__ float g_h[(size_t)NTOK*CC];        // fp32 residual-scaled hidden
// bf16 operands for tensor-core GEMMs / attention
__device__ __nv_bfloat16 g_qkvb[(size_t)NTOK*3*CC];
__device__ __nv_bfloat16 g_hcb [(size_t)NTOK*CC];
__device__ __nv_bfloat16 g_aob [(size_t)NTOK*CC];
__device__ __nv_bfloat16 g_hb  [(size_t)NTOK*CC];
__device__ __nv_bfloat16 g_midb[(size_t)NTOK*2*CC];
__device__ __nv_bfloat16 g_Winb [3*CC*CC];
__device__ __nv_bfloat16 g_Woutb[CC*CC];
__device__ __nv_bfloat16 g_Wm1b [2*CC*CC];
__device__ __nv_bfloat16 g_Wm2b [CC*2*CC];

// ---------------- helpers -----------------------------------------------------
__device__ __forceinline__ uint32_t smem_u32(const void* p){
    uint32_t a;
    asm("{ .reg .u64 t; cvta.to.shared.u64 t, %1; cvt.u32.u64 %0, t; }" : "=r"(a) : "l"(p));
    return a;
}
__device__ __forceinline__ uint32_t pk(float a, float b){
    __nv_bfloat162 t = __floats2bfloat162_rn(a, b);
    return *reinterpret_cast<uint32_t*>(&t);
}
__device__ __forceinline__ void ldsm4(uint32_t& r0, uint32_t& r1, uint32_t& r2, uint32_t& r3,
                                      uint32_t addr){
    asm volatile("ldmatrix.sync.aligned.m8n8.x4.shared.b16 {%0,%1,%2,%3}, [%4];"
                 : "=r"(r0), "=r"(r1), "=r"(r2), "=r"(r3) : "r"(addr));
}
__device__ __forceinline__ void mma_bf16(float* c, const uint32_t* a, const uint32_t* b){
    asm volatile("mma.sync.aligned.m16n8k16.row.col.f32.bf16.bf16.f32 "
                 "{%0,%1,%2,%3}, {%4,%5,%6,%7}, {%8,%9}, {%0,%1,%2,%3};"
                 : "+f"(c[0]), "+f"(c[1]), "+f"(c[2]), "+f"(c[3])
                 : "r"(a[0]), "r"(a[1]), "r"(a[2]), "r"(a[3]), "r"(b[0]), "r"(b[1]));
}
__device__ __forceinline__ void cp16(uint32_t dst, const void* src){
    asm volatile("cp.async.cg.shared.global [%0], [%1], 16;" :: "r"(dst), "l"(src) : "memory");
}
#define CP_COMMIT() asm volatile("cp.async.commit_group;" ::: "memory")
#define CP_WAIT0()  asm volatile("cp.async.wait_group 0;"  ::: "memory")
__device__ __forceinline__ void ffma2(uint64_t& c, uint64_t a, uint64_t b){
    asm volatile("fma.rn.f32x2 %0, %1, %2, %0;" : "+l"(c) : "l"(a), "l"(b));
}
__device__ __forceinline__ uint64_t pk64(float lo, float hi){
    uint64_t v;
    asm("mov.b64 %0, {%1, %2};" : "=l"(v) : "f"(lo), "f"(hi));
    return v;
}
__device__ __forceinline__ void unpk64(float& lo, float& hi, uint64_t v){
    asm("mov.b64 {%0, %1}, %2;" : "=f"(lo), "=f"(hi) : "l"(v));
}

// ---------------- warp-MMA bf16 GEMM (BK=32, 2-stage, static smem) -------------
// SKIPPAD: when the whole 128-row M-tile lies in the zero-padded region
// (j >= kper[batch]), skip loads+mainloop; epilogue with acc=0 writes exactly
// bias — bit-identical to the full GEMM of zero rows.
#define SROW 40                      // smem row stride in bf16 (padded, 80B)
#define STAGEB (128*SROW*2)          // stage size in bytes (10240)

template<int ACT, int RES, int OUTBF, int SCAT, int SKIPPAD>
__global__ __launch_bounds__(256)
void wmma_gemm(const __nv_bfloat16* __restrict__ A, const __nv_bfloat16* __restrict__ W,
               const float* __restrict__ bias, const float* __restrict__ res,
               float* __restrict__ outf, __nv_bfloat16* __restrict__ outb,
               const float* __restrict__ ratio,
               int M, int N, int K)
{
    __shared__ __align__(16) __nv_bfloat16 As[2*128*SROW];
    __shared__ __align__(16) __nv_bfloat16 Bs[2*128*SROW];
    const uint32_t as_b = smem_u32(As);
    const uint32_t bs_b = smem_u32(Bs);
    const int tid  = threadIdx.x;
    const int wid  = tid >> 5, lane = tid & 31;
    const int bm   = blockIdx.y << 7;
    const int bn   = blockIdx.x << 7;
    const int wm   = wid & 3;
    const int wn   = wid >> 2;

    float acc[2][8][4];
#pragma unroll
    for (int i = 0; i < 2; i++)
#pragma unroll
        for (int j = 0; j < 8; j++)
#pragma unroll
            for (int q = 0; q < 4; q++) acc[i][j][q] = 0.f;

    const uint32_t a_row = (uint32_t)(wm*32 + (lane & 15));
    const uint32_t a_kad = (uint32_t)((lane >> 4) << 3);
    const uint32_t b_row = (uint32_t)(wn*64 + ((lane >> 4) << 3) + (lane & 7));
    const uint32_t b_kad = (uint32_t)(((lane >> 3) & 1) << 3);

    bool skip = false;
    if (SKIPPAD) skip = ((bm & 511) >= g_kper[bm >> 9]);   // uniform per CTA

    if (!skip) {
        const int lrow0 = (tid >> 2);
        const int lch   = (tid & 3) << 3;
        const __nv_bfloat16* Ap0 = A + (size_t)(bm + lrow0     ) * K + lch;
        const __nv_bfloat16* Ap1 = A + (size_t)(bm + lrow0 + 64) * K + lch;
        const __nv_bfloat16* Wp0 = W + (size_t)(bn + lrow0     ) * K + lch;
        const __nv_bfloat16* Wp1 = W + (size_t)(bn + lrow0 + 64) * K + lch;
        const uint32_t soff0 = (uint32_t)(lrow0      * SROW + lch) * 2;
        const uint32_t soff1 = (uint32_t)((lrow0+64) * SROW + lch) * 2;

        const int nc = K >> 5;
        cp16(as_b + soff0, Ap0); cp16(as_b + soff1, Ap1);
        cp16(bs_b + soff0, Wp0); cp16(bs_b + soff1, Wp1);
        CP_COMMIT();

        for (int c = 0; c < nc; c++) {
            CP_WAIT0();
            __syncthreads();
            if (c + 1 < nc) {
                const int k1 = (c + 1) << 5;
                const uint32_t sb = ((c + 1) & 1) * STAGEB;
                cp16(as_b + sb + soff0, Ap0 + k1); cp16(as_b + sb + soff1, Ap1 + k1);
                cp16(bs_b + sb + soff0, Wp0 + k1); cp16(bs_b + sb + soff1, Wp1 + k1);
                CP_COMMIT();
            }
            const uint32_t ab = as_b + (c & 1) * STAGEB;
            const uint32_t bb = bs_b + (c & 1) * STAGEB;
#pragma unroll
            for (int ks = 0; ks < 2; ks++) {
                const uint32_t kcol = (uint32_t)(ks << 4);
                uint32_t a[2][4];
#pragma unroll
                for (int tm = 0; tm < 2; tm++) {
                    uint32_t ad = ab + ((a_row + tm*16) * SROW + kcol + a_kad) * 2;
                    ldsm4(a[tm][0], a[tm][1], a[tm][2], a[tm][3], ad);
                }
                uint32_t b[8][2];
#pragma unroll
                for (int tp = 0; tp < 4; tp++) {
                    uint32_t bd = bb + ((b_row + tp*16) * SROW + kcol + b_kad) * 2;
                    ldsm4(b[2*tp][0], b[2*tp][1], b[2*tp+1][0], b[2*tp+1][1], bd);
                }
#pragma unroll
                for (int tm = 0; tm < 2; tm++)
#pragma unroll
                    for (int tn = 0; tn < 8; tn++)
                        mma_bf16(acc[tm][tn], a[tm], b[tn]);
            }
            __syncthreads();
        }
    }

    if (SCAT) {
        const int kmax = g_kmax;
#pragma unroll
        for (int tm = 0; tm < 2; tm++) {
#pragma unroll
            for (int half = 0; half < 2; half++) {
                const int m = bm + wm*32 + tm*16 + (lane >> 2) + half*8;
                const int b = m >> 9, j = m & 511;
                if (j >= kmax) continue;
                const int dst = g_topk[m];
                const size_t node = (((size_t)b << 9) + dst) * CC;
                const float r = ratio[b];
#pragma unroll
                for (int tn = 0; tn < 8; tn++) {
                    const int gn = bn + wn*64 + tn*8 + ((lane & 3) << 1);
                    float v0 = acc[tm][tn][2*half+0] + bias[gn];
                    float v1 = acc[tm][tn][2*half+1] + bias[gn+1];
                    float2 xv = *(const float2*)(res + node + gn);
                    v0 = (v0 + xv.x) * r;
                    v1 = (v1 + xv.y) * r;
                    *(float2*)(g_h + node + gn) = make_float2(v0, v1);
                    *(uint32_t*)(g_hb + node + gn) = pk(v0, v1);
                }
            }
        }
        return;
    }

#pragma unroll
    for (int tm = 0; tm < 2; tm++) {
        const int gm = bm + wm*32 + tm*16 + (lane >> 2);
#pragma unroll
        for (int tn = 0; tn < 8; tn++) {
            const int gn = bn + wn*64 + tn*8 + ((lane & 3) << 1);
            const float b0 = bias[gn], b1 = bias[gn+1];
#pragma unroll
            for (int half = 0; half < 2; half++) {
                const int m = gm + half*8;
                float v0 = acc[tm][tn][2*half+0] + b0;
                float v1 = acc[tm][tn][2*half+1] + b1;
                if (ACT) { v0 = fmaxf(v0, 0.f); v1 = fmaxf(v1, 0.f); }
                const size_t o = (size_t)m * N + gn;
                if (RES) {
                    float2 r = *(const float2*)(res + o);
                    v0 += r.x; v1 += r.y;
                }
                if (OUTBF) *(uint32_t*)(outb + o) = pk(v0, v1);
                else       *(float2*)(outf + o)   = make_float2(v0, v1);
            }
        }
    }
}

// ---------------- scorer GEMM with fused score dot ----------------------------
__global__ __launch_bounds__(256)
void scorer_gemm(const float* __restrict__ A, const float* __restrict__ W,
                 const float* __restrict__ bias, const float* __restrict__ Ws2,
                 int M, int K)
{
    __shared__ float As[8][132];
    __shared__ float Bs[8][132];
    const int tid = threadIdx.x;
    const int tx = tid & 15, ty = tid >> 4;
    const int bm = blockIdx.y << 7, bn = blockIdx.x << 7;
    const int lr = tid >> 1;
    const int lc = (tid & 1) << 2;

    uint64_t acc2[8][4];
#pragma unroll
    for (int i = 0; i < 8; i++)
#pragma unroll
        for (int j = 0; j < 4; j++) acc2[i][j] = 0ull;

    const float* Ap = A + (size_t)(bm + lr) * K + lc;
    const float* Wp = W + (size_t)(bn + lr) * K + lc;

    float4 av = *(const float4*)Ap;
    float4 wv = *(const float4*)Wp;

    for (int k0 = 0; k0 < K; k0 += 8) {
        __syncthreads();
        As[lc+0][lr]=av.x; As[lc+1][lr]=av.y; As[lc+2][lr]=av.z; As[lc+3][lr]=av.w;
        Bs[lc+0][lr]=wv.x; Bs[lc+1][lr]=wv.y; Bs[lc+2][lr]=wv.z; Bs[lc+3][lr]=wv.w;
        __syncthreads();
        if (k0 + 8 < K) {
            av = *(const float4*)(Ap + k0 + 8);
            wv = *(const float4*)(Wp + k0 + 8);
        }
#pragma unroll
        for (int kk = 0; kk < 8; kk++) {
            float a[8], b[8];
            *(float4*)&a[0] = *(const float4*)&As[kk][ty*8];
            *(float4*)&a[4] = *(const float4*)&As[kk][ty*8+4];
            *(float4*)&b[0] = *(const float4*)&Bs[kk][tx*8];
            *(float4*)&b[4] = *(const float4*)&Bs[kk][tx*8+4];
            uint64_t bp[4];
#pragma unroll
            for (int j = 0; j < 4; j++) bp[j] = pk64(b[2*j], b[2*j+1]);
#pragma unroll
            for (int i = 0; i < 8; i++) {
                const uint64_t ad = pk64(a[i], a[i]);
#pragma unroll
                for (int j = 0; j < 4; j++)
                    ffma2(acc2[i][j], ad, bp[j]);
            }
        }
    }

    const int nb = bn + tx*8;
    float w2[8];
#pragma unroll
    for (int j = 0; j < 8; j++) w2[j] = Ws2[nb + j];
    const float bi[8] = { bias[nb], bias[nb+1], bias[nb+2], bias[nb+3],
                          bias[nb+4], bias[nb+5], bias[nb+6], bias[nb+7] };

    float rowp[8];
#pragma unroll
    for (int i = 0; i < 8; i++) {
        float v[8];
        unpk64(v[0], v[1], acc2[i][0]);
        unpk64(v[2], v[3], acc2[i][1]);
        unpk64(v[4], v[5], acc2[i][2]);
        unpk64(v[6], v[7], acc2[i][3]);
        float p = 0.f;
#pragma unroll
        for (int j = 0; j < 8; j++)
            p = fmaf(fmaxf(v[j] + bi[j], 0.f), w2[j], p);
        rowp[i] = p;
    }
#pragma unroll
    for (int i = 0; i < 8; i++) {
#pragma unroll
        for (int off = 8; off; off >>= 1)
            rowp[i] += __shfl_xor_sync(0xffffffffu, rowp[i], off);
    }
    if (tx == 0) {
        const int mbase = bm + ty*8;
#pragma unroll
        for (int i = 0; i < 8; i++)
            g_zpart[blockIdx.x * NTOK + mbase + i] = rowp[i];
    }
}

// ---------------- weights fp32->bf16 (4 segs) + kper/kmax (block 512) ---------
__global__ __launch_bounds__(256)
void f2bf4_kernel(const float* __restrict__ Win,  __nv_bfloat16* __restrict__ dWin,
                  const float* __restrict__ Wout, __nv_bfloat16* __restrict__ dWout,
                  const float* __restrict__ Wm1,  __nv_bfloat16* __restrict__ dWm1,
                  const float* __restrict__ Wm2,  __nv_bfloat16* __restrict__ dWm2,
                  const float* __restrict__ ratio)
{
    int blk = blockIdx.x;
    if (blk == 512) {
        __shared__ int sm[64];
        int t = threadIdx.x;
        if (t < 64) {
            int kp = (int)ceilf(ratio[t] * 512.0f);
            if (kp < 1)  kp = 1;
            if (kp > LL) kp = LL;
            g_kper[t] = kp;
            sm[t] = kp;
        }
        __syncthreads();
        for (int s = 32; s > 0; s >>= 1) {
            if (t < s) sm[t] = max(sm[t], sm[t+s]);
            __syncthreads();
        }
        if (t == 0) g_kmax = sm[0];
        return;
    }
    const float* s; __nv_bfloat16* d; int off;
    if      (blk < 192) { s = Win;  d = dWin;  off = blk;       }
    else if (blk < 256) { s = Wout; d = dWout; off = blk - 192; }
    else if (blk < 384) { s = Wm1;  d = dWm1;  off = blk - 256; }
    else                { s = Wm2;  d = dWm2;  off = blk - 384; }
    int i = off * 256 + threadIdx.x;
    float4 v = ((const float4*)s)[i];
    uint2 p; p.x = pk(v.x, v.y); p.y = pk(v.z, v.w);
    ((uint2*)d)[i] = p;
}

// ---------------- jax-replicated softmax pipeline + tier flag -----------------
__global__ __launch_bounds__(512)
void softmax_kernel(const float* __restrict__ gumbel, const float* __restrict__ bs2)
{
    __shared__ float red[512];
    const int b = blockIdx.x, t = threadIdx.x;
    const int n = b * 512 + t;
    float sc = __fadd_rn(__fadd_rn(g_zpart[n], g_zpart[NTOK + n]), bs2[0]);

    red[t] = sc; __syncthreads();
#pragma unroll
    for (int s = 256; s; s >>= 1) { if (t < s) red[t] = fmaxf(red[t], red[t+s]); __syncthreads(); }
    float m1 = red[0]; __syncthreads();

    float sh = __fadd_rn(sc, -m1);
    float e1 = expf(sh);
    red[t] = e1; __syncthreads();
#pragma unroll
    for (int s = 256; s; s >>= 1) { if (t < s) red[t] = __fadd_rn(red[t], red[t+s]); __syncthreads(); }
    float L = logf(red[0]); __syncthreads();

    float ls = __fadd_rn(sh, -L);
    float z  = __fadd_rn(ls, gumbel[n]);
    red[t] = z; __syncthreads();
#pragma unroll
    for (int s = 256; s; s >>= 1) { if (t < s) red[t] = fmaxf(red[t], red[t+s]); __syncthreads(); }
    float m2 = red[0]; __syncthreads();

    float e2 = expf(__fadd_rn(z, -m2));
    red[t] = e2; __syncthreads();
#pragma unroll
    for (int s = 256; s; s >>= 1) { if (t < s) red[t] = __fadd_rn(red[t], red[t+s]); __syncthreads(); }
    float S = red[0];

    float sval = __fdiv_rn(e2, S);
    g_sv[n] = sval;
    float tt = __fadd_rn(__fadd_rn(1.0f, sval), -sval);
    g_tier2[n] = (tt != 1.0f) ? 1 : 0;
}

// ---------------- per-batch selection: packed-key bitonic sort ----------------
// key = (fp32 bits << 32) | ~idx  — y_soft >= 0 so bit order == numeric order;
// descending key order == (value desc, idx asc) == jax top_k tie-breaking.
__global__ __launch_bounds__(512)
void topk_kernel()
{
    __shared__ uint64_t sk[512];
    __shared__ int sfl[512];
    __shared__ int sA[512];
    const int b = blockIdx.x, t = threadIdx.x;
    {
        uint32_t fb = __float_as_uint(g_sv[b*512 + t]);
        sk[t] = ((uint64_t)fb << 32) | (uint32_t)(~t);
    }
    __syncthreads();
    for (int k = 2; k <= 512; k <<= 1) {
        for (int j = k >> 1; j > 0; j >>= 1) {
            int ixj = t ^ j;
            if (ixj > t) {
                bool desc = ((t & k) == 0);
                uint64_t k1 = sk[t], k2 = sk[ixj];
                bool sw = desc ? (k1 < k2) : (k1 > k2);
                if (sw) { sk[t] = k2; sk[ixj] = k1; }
            }
            __syncthreads();
        }
    }
    const int kmax = g_kmax;
    const int kper = g_kper[b];
    const int sidx = (int)(~(uint32_t)sk[t]);   // original index at sorted rank t
    sfl[sidx] = (t < kmax) ? 1 : 0;
    __syncthreads();
    const int sel   = sfl[t];
    const int tier2 = (int)g_tier2[b*512 + t];
    const int a1 = sel & (tier2 ^ 1);
    const int a2 = sel & tier2;
    sA[t] = a1 | (a2 << 16);
    __syncthreads();
    for (int off = 1; off < 512; off <<= 1) {
        int add = (t >= off) ? sA[t-off] : 0;
        __syncthreads();
        sA[t] += add;
        __syncthreads();
    }
    const int inc1 = sA[t] & 0xffff, inc2 = sA[t] >> 16;
    const int n1   = sA[511] & 0xffff;
    const int excl1 = inc1 - a1, excl2 = inc2 - a2;
    const int kept = (a1 && excl1 < kper) || (a2 && (n1 + excl2) < kper);
    const int nk = 1 - kept;
    __syncthreads();
    sA[t] = kept | (nk << 16);
    __syncthreads();
    for (int off = 1; off < 512; off <<= 1) {
        int add = (t >= off) ? sA[t-off] : 0;
        __syncthreads();
        sA[t] += add;
        __syncthreads();
    }
    const int rk = (sA[t] & 0xffff) - kept;
    const int rn = (sA[t] >> 16) - nk;
    if (kept) g_topk[b*512 + rk] = t;
    else      g_topk[b*512 + kper + rn] = t;
}

// ---------------- gather (blocks [0, NTOK/4)) + hbase (rest) ------------------
__global__ __launch_bounds__(256)
void gather_hbase_kernel(const float* __restrict__ x, const float* __restrict__ ratio)
{
    const int blk = blockIdx.x;
    if (blk < NTOK/4) {
        int row = blk * 4 + (threadIdx.x >> 6);
        int b = row >> 9, j = row & 511;
        int t = threadIdx.x & 63;
        uint2* dst = (uint2*)(g_hcb + (size_t)row * CC);
        if (j < g_kper[b]) {
            int src = g_topk[row];
            float4 v = ((const float4*)(x + ((size_t)b*512 + src) * CC))[t];
            uint2 o; o.x = pk(v.x, v.y); o.y = pk(v.z, v.w);
            dst[t] = o;
        } else {
            dst[t] = make_uint2(0u, 0u);
        }
    } else {
        int i = (blk - NTOK/4) * 256 + threadIdx.x;   // float4 index
        int b = i >> 15;
        float r = ratio[b];
        float4 v = ((const float4*)x)[i];
        float4 o = make_float4(v.x*r, v.y*r, v.z*r, v.w*r);
        ((float4*)g_h)[i] = o;
        uint2 p; p.x = pk(o.x, o.y); p.y = pk(o.z, o.w);
        ((uint2*)g_hb)[i] = p;
    }
}

// ---------------- flash attention v2 on HMMA (bf16 in, fp32 accum) ------------
#define QS 40   // Q/K smem stride (bf16)
#define VS 72   // Vt smem stride (bf16)
__global__ __launch_bounds__(128)
void attn_mma_kernel()
{
    __shared__ __align__(16) __nv_bfloat16 Qs[64*QS];
    __shared__ __align__(16) __nv_bfloat16 Ks[64*QS];
    __shared__ __align__(16) __nv_bfloat16 Vt[32*VS];
    const uint32_t qs_b = smem_u32(Qs);
    const uint32_t ks_b = smem_u32(Ks);
    const uint32_t vt_b = smem_u32(Vt);

    const int bh = blockIdx.x;
    const int b = bh >> 3, h = bh & 7;
    const int q0 = blockIdx.y << 6;
    const int tid = threadIdx.x;
    const int wid = tid >> 5, lane = tid & 31;
    const int kper = g_kper[b];
    const size_t base = (size_t)b * 512;
    const int hq = h * 32;

#pragma unroll
    for (int i = 0; i < 2; i++) {
        int idx = tid + i*128;
        int row = idx >> 2, qt = idx & 3;
        const uint4 v = *(const uint4*)(g_qkvb + (base + q0 + row) * 768 + hq + qt*8);
        *(uint4*)((char*)Qs + (row*QS + qt*8)*2) = v;
    }

    const uint32_t a_row = (uint32_t)(wid*16 + (lane & 15));
    const uint32_t a_kad = (uint32_t)((lane >> 4) << 3);
    const uint32_t b_rw  = (uint32_t)(((lane >> 4) << 3) + (lane & 7));
    const uint32_t b_kad = (uint32_t)(((lane >> 3) & 1) << 3);
    __syncthreads();
    uint32_t aq[2][4];
#pragma unroll
    for (int ks = 0; ks < 2; ks++)
        ldsm4(aq[ks][0], aq[ks][1], aq[ks][2], aq[ks][3],
              qs_b + (a_row*QS + ks*16 + a_kad)*2);

    float co[4][4];
#pragma unroll
    for (int i = 0; i < 4; i++)
#pragma unroll
        for (int j = 0; j < 4; j++) co[i][j] = 0.f;
    float m0 = -1e30f, m1 = -1e30f, l0 = 0.f, l1 = 0.f;
    const float scale = 0.17677669529663687f;
    const int colb = (lane & 3) << 1;

    for (int kt = 0; kt < kper; kt += 64) {
        __syncthreads();
#pragma unroll
        for (int i = 0; i < 2; i++) {
            int idx = tid + i*128;
            int row = idx >> 2, qt = idx & 3;
            int rk = min(kt + row, 511);
            const uint4 v = *(const uint4*)(g_qkvb + (base + rk) * 768 + 256 + hq + qt*8);
            *(uint4*)((char*)Ks + (row*QS + qt*8)*2) = v;
        }
#pragma unroll
        for (int i = 0; i < 4; i++) {
            int idx = tid + i*128;
            int key = idx >> 3, dg = (idx & 7) << 2;
            int rk = min(kt + key, 511);
            const uint2 v = *(const uint2*)(g_qkvb + (base + rk) * 768 + 512 + hq + dg);
            const __nv_bfloat16* pv = (const __nv_bfloat16*)&v;
            Vt[(dg+0)*VS + key] = pv[0];
            Vt[(dg+1)*VS + key] = pv[1];
            Vt[(dg+2)*VS + key] = pv[2];
            Vt[(dg+3)*VS + key] = pv[3];
        }
        __syncthreads();

        float cs[8][4];
#pragma unroll
        for (int nt = 0; nt < 8; nt++)
#pragma unroll
            for (int e = 0; e < 4; e++) cs[nt][e] = 0.f;
#pragma unroll
        for (int ks = 0; ks < 2; ks++) {
            uint32_t bk[8][2];
#pragma unroll
            for (int tp = 0; tp < 4; tp++) {
                uint32_t bd = ks_b + ((tp*16 + b_rw)*QS + ks*16 + b_kad)*2;
                ldsm4(bk[2*tp][0], bk[2*tp][1], bk[2*tp+1][0], bk[2*tp+1][1], bd);
            }
#pragma unroll
            for (int nt = 0; nt < 8; nt++)
                mma_bf16(cs[nt], aq[ks], bk[nt]);
        }
#pragma unroll
        for (int nt = 0; nt < 8; nt++) {
            int k0e = kt + nt*8 + colb;
#pragma unroll
            for (int e = 0; e < 4; e++) {
                float s = cs[nt][e] * scale;
                cs[nt][e] = (k0e + (e & 1) < kper) ? s : -1e30f;
            }
        }
        float mx0 = -1e30f, mx1 = -1e30f;
#pragma unroll
        for (int nt = 0; nt < 8; nt++) {
            mx0 = fmaxf(mx0, fmaxf(cs[nt][0], cs[nt][1]));
            mx1 = fmaxf(mx1, fmaxf(cs[nt][2], cs[nt][3]));
        }
        mx0 = fmaxf(mx0, __shfl_xor_sync(0xffffffffu, mx0, 1));
        mx0 = fmaxf(mx0, __shfl_xor_sync(0xffffffffu, mx0, 2));
        mx1 = fmaxf(mx1, __shfl_xor_sync(0xffffffffu, mx1, 1));
        mx1 = fmaxf(mx1, __shfl_xor_sync(0xffffffffu, mx1, 2));
        float mn0 = fmaxf(m0, mx0), mn1 = fmaxf(m1, mx1);
        float sf0 = __expf(m0 - mn0), sf1 = __expf(m1 - mn1);
        m0 = mn0; m1 = mn1;
        l0 *= sf0; l1 *= sf1;
#pragma unroll
        for (int nt = 0; nt < 4; nt++) {
            co[nt][0] *= sf0; co[nt][1] *= sf0;
            co[nt][2] *= sf1; co[nt][3] *= sf1;
        }
        uint32_t pa[4][4];
#pragma unroll
        for (int nt = 0; nt < 8; nt++) {
            float p0 = __expf(cs[nt][0] - m0);
            float p1 = __expf(cs[nt][1] - m0);
            float p2 = __expf(cs[nt][2] - m1);
            float p3 = __expf(cs[nt][3] - m1);
            l0 += p0 + p1; l1 += p2 + p3;
            int kc = nt >> 1, hi = (nt & 1) << 1;
            pa[kc][hi+0] = pk(p0, p1);
            pa[kc][hi+1] = pk(p2, p3);
        }
#pragma unroll
        for (int kc = 0; kc < 4; kc++) {
            uint32_t bv[4][2];
#pragma unroll
            for (int np = 0; np < 2; np++) {
                uint32_t vd = vt_b + ((np*16 + b_rw)*VS + kc*16 + b_kad)*2;
                ldsm4(bv[2*np][0], bv[2*np][1], bv[2*np+1][0], bv[2*np+1][1], vd);
            }
#pragma unroll
            for (int nt = 0; nt < 4; nt++)
                mma_bf16(co[nt], pa[kc], bv[nt]);
        }
    }
    l0 += __shfl_xor_sync(0xffffffffu, l0, 1);
    l0 += __shfl_xor_sync(0xffffffffu, l0, 2);
    l1 += __shfl_xor_sync(0xffffffffu, l1, 1);
    l1 += __shfl_xor_sync(0xffffffffu, l1, 2);
    float inv0 = 1.f / l0, inv1 = 1.f / l1;
    const int r0 = q0 + wid*16 + (lane >> 2);
#pragma unroll
    for (int nt = 0; nt < 4; nt++) {
        const int col = hq + nt*8 + colb;
        *(uint32_t*)(g_aob + (base + r0    ) * CC + col) = pk(co[nt][0]*inv0, co[nt][1]*inv0);
        *(uint32_t*)(g_aob + (base + r0 + 8) * CC + col) = pk(co[nt][2]*inv1, co[nt][3]*inv1);
    }
}

// ------------------------------------------------------------------------------
extern "C" void kernel_launch(void* const* d_in, const int* in_sizes, int n_in,
                              void* d_out, int out_size)
{
    (void)in_sizes; (void)n_in; (void)out_size;
    const float* x      = (const float*)d_in[0];
    const float* ratio  = (const float*)d_in[3];
    const float* gumbel = (const float*)d_in[4];
    const float* Ws1    = (const float*)d_in[5];
    const float* bs1    = (const float*)d_in[6];
    const float* Ws2    = (const float*)d_in[7];
    const float* bs2    = (const float*)d_in[8];
    const float* Win    = (const float*)d_in[9];
    const float* b_in   = (const float*)d_in[10];
    const float* Wout   = (const float*)d_in[11];
    const float* bout   = (const float*)d_in[12];
    const float* Wm1    = (const float*)d_in[13];
    const float* bm1    = (const float*)d_in[14];
    const float* Wm2    = (const float*)d_in[15];
    const float* bm2    = (const float*)d_in[16];
    float* out = (float*)d_out;

    float *hp;
    __nv_bfloat16 *qkvbp, *hcbp, *aobp, *hbp, *midbp, *winbp, *woutbp, *wm1bp, *wm2bp;
    cudaGetSymbolAddress((void**)&hp,     g_h);
    cudaGetSymbolAddress((void**)&qkvbp,  g_qkvb);
    cudaGetSymbolAddress((void**)&hcbp,   g_hcb);
    cudaGetSymbolAddress((void**)&aobp,   g_aob);
    cudaGetSymbolAddress((void**)&hbp,    g_hb);
    cudaGetSymbolAddress((void**)&midbp,  g_midb);
    cudaGetSymbolAddress((void**)&winbp,  g_Winb);
    cudaGetSymbolAddress((void**)&woutbp, g_Woutb);
    cudaGetSymbolAddress((void**)&wm1bp,  g_Wm1b);
    cudaGetSymbolAddress((void**)&wm2bp,  g_Wm2b);

    // weight conversions + kper/kmax (single launch)
    f2bf4_kernel<<<513, 256>>>(Win, winbp, Wout, woutbp, Wm1, wm1bp, Wm2, wm2bp, ratio);

    // 1. scorer GEMM with fused score dot -> g_zpart
    scorer_gemm<<<dim3(CC/128, NTOK/128), 256>>>(x, Ws1, bs1, Ws2, NTOK, CC);
    softmax_kernel<<<BB, 512>>>(gumbel, bs2);
    topk_kernel<<<BB, 512>>>();
    // 2. gather (bf16) + h base (fused; must precede Wout-scatter)
    gather_hbase_kernel<<<NTOK/4 + (NTOK*CC/4)/256, 256>>>(x, ratio);
    // 3. qkv = h_compact @ Win^T + b_in  (HMMA, bf16 out, padding tiles skipped)
    wmma_gemm<0,0,1,0,1><<<dim3(6, NTOK/128), 256>>>(hcbp, winbp, b_in, nullptr,
                                                     nullptr, qkvbp, nullptr, NTOK, 3*CC, CC);
    // 4. attention (HMMA flash-attn, bf16 out)
    attn_mma_kernel<<<dim3(BB*HH, 8), 128>>>();
    // 5. Wout GEMM with fused scatter: h[topk] = (ao@Wout^T + bout + x)*ratio
    wmma_gemm<0,0,0,1,0><<<dim3(2, NTOK/128), 256>>>(aobp, woutbp, bout, x,
                                                     nullptr, nullptr, ratio, NTOK, CC, CC);
    // 6. mid = relu(h @ Wm1^T + bm1)  (bf16 out)
    wmma_gemm<1,0,1,0,0><<<dim3(4, NTOK/128), 256>>>(hbp, wm1bp, bm1, nullptr,
                                                     nullptr, midbp, nullptr, NTOK, 2*CC, CC);
    // 7. out = h + mid @ Wm2^T + bm2
    wmma_gemm<0,1,0,0,0><<<dim3(2, NTOK/128), 256>>>(midbp, wm2bp, bm2, hp,
                                                     out, nullptr, nullptr, NTOK, CC, 2*CC);
}